// round 14
// baseline (speedup 1.0000x reference)
#include <cuda_runtime.h>
#include <cuda_fp16.h>
#include <math.h>
#include <cstdint>

#define B_    8
#define L_    4096
#define D_    384
#define DI_   768
#define S_    16
#define DTR_  24
#define KC_   4
#define NC_   40
#define T_    (B_*L_)          // 32768 tokens
#define XDN_  (DTR_ + 2*S_)    // 56
#define NI_   (2*DI_)          // 1536
#define EPS_  1e-5f
#define NCHK_ 4
#define CL_   (L_/NCHK_)       // 1024
#define NST_  (B_*DI_*S_)     // 98304 state floats per chunk boundary

// ======================= mma / async helpers =======================
__device__ __forceinline__ uint32_t f2tf32(float x) {
    uint32_t r; asm("cvt.rna.tf32.f32 %0, %1;" : "=r"(r) : "f"(x)); return r;
}
__device__ __forceinline__ void mma_tf32(float* c, const uint32_t* a, const uint32_t* b) {
    asm volatile(
        "mma.sync.aligned.m16n8k8.row.col.f32.tf32.tf32.f32 "
        "{%0,%1,%2,%3}, {%4,%5,%6,%7}, {%8,%9}, {%0,%1,%2,%3};\n"
        : "+f"(c[0]), "+f"(c[1]), "+f"(c[2]), "+f"(c[3])
        : "r"(a[0]), "r"(a[1]), "r"(a[2]), "r"(a[3]), "r"(b[0]), "r"(b[1]));
}
__device__ __forceinline__ void mma_f16(float* c, const uint32_t* a, const uint32_t* b) {
    asm volatile(
        "mma.sync.aligned.m16n8k16.row.col.f32.f16.f16.f32 "
        "{%0,%1,%2,%3}, {%4,%5,%6,%7}, {%8,%9}, {%0,%1,%2,%3};\n"
        : "+f"(c[0]), "+f"(c[1]), "+f"(c[2]), "+f"(c[3])
        : "r"(a[0]), "r"(a[1]), "r"(a[2]), "r"(a[3]), "r"(b[0]), "r"(b[1]));
}
__device__ __forceinline__ void ldsm_x4(uint32_t& r0, uint32_t& r1, uint32_t& r2, uint32_t& r3,
                                        uint32_t addr) {
    asm volatile("ldmatrix.sync.aligned.m8n8.x4.shared.b16 {%0,%1,%2,%3}, [%4];"
        : "=r"(r0), "=r"(r1), "=r"(r2), "=r"(r3) : "r"(addr));
}
__device__ __forceinline__ void ldsm_x2(uint32_t& r0, uint32_t& r1, uint32_t addr) {
    asm volatile("ldmatrix.sync.aligned.m8n8.x2.shared.b16 {%0,%1}, [%2];"
        : "=r"(r0), "=r"(r1) : "r"(addr));
}
__device__ __forceinline__ void cp_async16(uint32_t saddr, const void* g) {
    asm volatile("cp.async.cg.shared.global [%0], [%1], 16;\n" :: "r"(saddr), "l"(g));
}
#define CP_COMMIT() asm volatile("cp.async.commit_group;\n" ::: "memory")
#define CP_WAIT(n)  asm volatile("cp.async.wait_group %0;\n" :: "n"(n) : "memory")

// ======================= scratch =======================
__device__ __align__(128) __half g_xnh [T_ * D_];        // rmsnorm output (half)
__device__ __align__(128) __half g_wth [NI_ * D_];       // W_in^T (half)
__device__ __align__(128) __half g_xzh [T_ * NI_];       // xn @ W_in (xp | z), HALF
__device__ __align__(128) __half g_xch [T_ * DI_];       // conv+silu output (half)
__device__ __align__(128) float  g_wt2 [64 * DI_];       // W_xproj^T zero-padded
__device__ __align__(128) float  g_xdbl[T_ * XDN_];      // xc @ W_xproj
__device__ __align__(128) __half g_dth [T_ * DI_];       // softplus dt (half)
__device__ __align__(128) float  g_bc  [T_ * S_ * 2];    // (B, C) interleaved
__device__ __align__(128) __half g_yh  [T_ * DI_];       // scan output (half)
__device__ __align__(128) float  g_se [3 * NST_];        // chunk-local end states
__device__ __align__(128) float  g_sp [3 * NST_];        // chunk dA products
__device__ __align__(128) float  g_hs [3 * NST_];        // chunk start states
__device__ float g_ypart[64 * B_ * DI_];
__device__ float g_xpart[64 * B_ * D_];
__device__ float g_ym   [B_ * DI_];
__device__ float g_xmean[B_ * D_];
__device__ float g_pooled[B_ * D_];

// ======================= RMSNorm -> half =======================
__global__ void k_rmsnorm(const float* __restrict__ x, const float* __restrict__ ln_w) {
    int t = blockIdx.x;
    const float* xr = x + (size_t)t * D_;
    float ss = 0.f;
    for (int d = threadIdx.x; d < D_; d += 128) { float v = xr[d]; ss += v * v; }
    #pragma unroll
    for (int o = 16; o; o >>= 1) ss += __shfl_xor_sync(0xffffffffu, ss, o);
    __shared__ float sw[4];
    if ((threadIdx.x & 31) == 0) sw[threadIdx.x >> 5] = ss;
    __syncthreads();
    float tot = sw[0] + sw[1] + sw[2] + sw[3];
    float rs = rsqrtf(tot * (1.f / D_) + EPS_);
    for (int d = threadIdx.x; d < D_; d += 128)
        g_xnh[(size_t)t * D_ + d] = __float2half_rn(xr[d] * rs * ln_w[d]);
}

// ======================= W_in transpose -> half =======================
__global__ void k_wt(const float* __restrict__ W_in) {
    __shared__ float tile[32][33];
    int k0 = blockIdx.x * 32, n0 = blockIdx.y * 32;
    int tx = threadIdx.x & 31, ty = threadIdx.x >> 5;
    for (int i = 0; i < 32; i += 8)
        tile[ty + i][tx] = W_in[(size_t)(k0 + ty + i) * NI_ + n0 + tx];
    __syncthreads();
    for (int i = 0; i < 32; i += 8)
        g_wth[(size_t)(n0 + ty + i) * D_ + k0 + tx] = __float2half_rn(tile[tx][ty + i]);
}

// ======================= W_xproj transpose, zero-padded to 64 rows =======================
__global__ void k_wt2(const float* __restrict__ W) {
    __shared__ float tile[32][33];
    int k0 = blockIdx.x * 32, n0 = blockIdx.y * 32;
    int tx = threadIdx.x & 31, ty = threadIdx.x >> 5;
    for (int i = 0; i < 32; i += 8)
        tile[ty + i][tx] = (n0 + tx < XDN_) ? W[(size_t)(k0 + ty + i) * XDN_ + n0 + tx] : 0.f;
    __syncthreads();
    for (int i = 0; i < 32; i += 8)
        g_wt2[(size_t)(n0 + ty + i) * DI_ + k0 + tx] = tile[tx][ty + i];
}

// ======================= GEMM1: fp16 mma + cp.async 2-stage, BK=64, ldmatrix =====
#define G1P_   72
#define G1ST_  (128 * G1P_ * 2)
#define G1SM_  (4 * G1ST_)

__global__ void __launch_bounds__(256, 2) k_gemm1(const __half* __restrict__ A,
                                                  const __half* __restrict__ Bt,
                                                  __half* __restrict__ C) {
    extern __shared__ __half g1s[];
    int tid = threadIdx.x;
    int lane = tid & 31, wid = tid >> 5;
    int wm = wid >> 2, wn = wid & 3;
    int gid = lane >> 2, tig = lane & 3;
    int m0 = blockIdx.y * 128, n0 = blockIdx.x * 128;

    uint32_t sa0 = (uint32_t)__cvta_generic_to_shared(&g1s[0]);
    uint32_t sb0 = sa0 + 2 * G1ST_;

    int a_row = ((lane >> 3) & 1) * 8 + (lane & 7);
    int a_kof = (lane >> 4) * 8;
    int b_row = lane & 7;
    int b_kof = ((lane >> 3) & 1) * 8;

    float acc[4][4][4];
    #pragma unroll
    for (int i = 0; i < 4; i++)
        #pragma unroll
        for (int j = 0; j < 4; j++)
            #pragma unroll
            for (int q = 0; q < 4; q++) acc[i][j][q] = 0.f;

    #pragma unroll
    for (int i = 0; i < 4; i++) {
        int f = tid + i * 256;
        int row = f >> 3, c8 = f & 7;
        cp_async16(sa0 + row * (G1P_ * 2) + c8 * 16,
                   &A[(size_t)(m0 + row) * D_ + c8 * 8]);
        cp_async16(sb0 + row * (G1P_ * 2) + c8 * 16,
                   &Bt[(size_t)(n0 + row) * D_ + c8 * 8]);
    }
    CP_COMMIT();

    for (int c = 0; c < 6; c++) {
        int cur = c & 1;
        if (c < 5) {
            int nxt = (c + 1) & 1;
            #pragma unroll
            for (int i = 0; i < 4; i++) {
                int f = tid + i * 256;
                int row = f >> 3, c8 = f & 7;
                cp_async16(sa0 + nxt * G1ST_ + row * (G1P_ * 2) + c8 * 16,
                           &A[(size_t)(m0 + row) * D_ + (c + 1) * 64 + c8 * 8]);
                cp_async16(sb0 + nxt * G1ST_ + row * (G1P_ * 2) + c8 * 16,
                           &Bt[(size_t)(n0 + row) * D_ + (c + 1) * 64 + c8 * 8]);
            }
            CP_COMMIT();
            CP_WAIT(1);
        } else {
            CP_WAIT(0);
        }
        __syncthreads();
        uint32_t pa = sa0 + cur * G1ST_;
        uint32_t pb = sb0 + cur * G1ST_;
        #pragma unroll
        for (int kk = 0; kk < 64; kk += 16) {
            uint32_t af[4][4], bf[4][2];
            #pragma unroll
            for (int mt = 0; mt < 4; mt++) {
                int r = wm * 64 + mt * 16 + a_row;
                ldsm_x4(af[mt][0], af[mt][1], af[mt][2], af[mt][3],
                        pa + r * (G1P_ * 2) + (kk + a_kof) * 2);
            }
            #pragma unroll
            for (int nt = 0; nt < 4; nt++) {
                int r = wn * 32 + nt * 8 + b_row;
                ldsm_x2(bf[nt][0], bf[nt][1],
                        pb + r * (G1P_ * 2) + (kk + b_kof) * 2);
            }
            #pragma unroll
            for (int mt = 0; mt < 4; mt++)
                #pragma unroll
                for (int nt = 0; nt < 4; nt++)
                    mma_f16(acc[mt][nt], af[mt], bf[nt]);
        }
        __syncthreads();
    }
    #pragma unroll
    for (int mt = 0; mt < 4; mt++) {
        int row = m0 + wm * 64 + mt * 16 + gid;
        #pragma unroll
        for (int nt = 0; nt < 4; nt++) {
            int col = n0 + wn * 32 + nt * 8 + 2 * tig;
            *(__half2*)&C[(size_t)row * NI_ + col] =
                __floats2half2_rn(acc[mt][nt][0], acc[mt][nt][1]);
            *(__half2*)&C[(size_t)(row + 8) * NI_ + col] =
                __floats2half2_rn(acc[mt][nt][2], acc[mt][nt][3]);
        }
    }
}

// ======================= GEMM2: tf32 mma, x_dbl[T,56] = xc(half)[T,768] @ W_xproj ==========
#define G2P_ 36

__global__ void __launch_bounds__(256, 2) k_gemm2(const __half* __restrict__ A,
                                                  const float* __restrict__ Bt,
                                                  float* __restrict__ C) {
    __shared__ uint32_t sA[128 * G2P_];
    __shared__ uint32_t sB[64 * G2P_];
    int tid = threadIdx.x;
    int lane = tid & 31, wid = tid >> 5;
    int wm = wid >> 1, wn = wid & 1;
    int gid = lane >> 2, tig = lane & 3;
    int m0 = blockIdx.x * 128;

    float acc[2][4][4];
    #pragma unroll
    for (int i = 0; i < 2; i++)
        #pragma unroll
        for (int j = 0; j < 4; j++)
            #pragma unroll
            for (int q = 0; q < 4; q++) acc[i][j][q] = 0.f;

    for (int k0 = 0; k0 < DI_; k0 += 32) {
        #pragma unroll
        for (int i = 0; i < 2; i++) {
            int f = tid + i * 256;
            int row = f >> 2, c16 = f & 3;
            float4 v = *(const float4*)&A[(size_t)(m0 + row) * DI_ + k0 + c16 * 8];
            const __half2* hp = (const __half2*)&v;
            uint32_t* d = &sA[row * G2P_ + c16 * 8];
            #pragma unroll
            for (int q = 0; q < 4; q++) {
                float2 f2 = __half22float2(hp[q]);
                d[2 * q]     = f2tf32(f2.x);
                d[2 * q + 1] = f2tf32(f2.y);
            }
        }
        #pragma unroll
        for (int i = 0; i < 2; i++) {
            int f = tid + i * 256;
            int row = f >> 3, c4 = f & 7;
            float4 v = *(const float4*)&Bt[(size_t)row * DI_ + k0 + c4 * 4];
            uint32_t* d = &sB[row * G2P_ + c4 * 4];
            d[0] = f2tf32(v.x); d[1] = f2tf32(v.y); d[2] = f2tf32(v.z); d[3] = f2tf32(v.w);
        }
        __syncthreads();
        #pragma unroll
        for (int kk = 0; kk < 32; kk += 8) {
            uint32_t af[2][4], bf[4][2];
            #pragma unroll
            for (int mt = 0; mt < 2; mt++) {
                int r = wm * 32 + mt * 16 + gid;
                af[mt][0] = sA[r * G2P_ + kk + tig];
                af[mt][1] = sA[(r + 8) * G2P_ + kk + tig];
                af[mt][2] = sA[r * G2P_ + kk + tig + 4];
                af[mt][3] = sA[(r + 8) * G2P_ + kk + tig + 4];
            }
            #pragma unroll
            for (int nt = 0; nt < 4; nt++) {
                int r = wn * 32 + nt * 8 + gid;
                bf[nt][0] = sB[r * G2P_ + kk + tig];
                bf[nt][1] = sB[r * G2P_ + kk + tig + 4];
            }
            #pragma unroll
            for (int mt = 0; mt < 2; mt++)
                #pragma unroll
                for (int nt = 0; nt < 4; nt++)
                    mma_tf32(acc[mt][nt], af[mt], bf[nt]);
        }
        __syncthreads();
    }
    #pragma unroll
    for (int mt = 0; mt < 2; mt++) {
        int row = m0 + wm * 32 + mt * 16 + gid;
        #pragma unroll
        for (int nt = 0; nt < 4; nt++) {
            int col = wn * 32 + nt * 8 + 2 * tig;
            if (col < XDN_) {
                *(float2*)&C[(size_t)row * XDN_ + col]       = make_float2(acc[mt][nt][0], acc[mt][nt][1]);
                *(float2*)&C[(size_t)(row + 8) * XDN_ + col] = make_float2(acc[mt][nt][2], acc[mt][nt][3]);
            }
        }
    }
}

// ======================= conv (K=4) + SiLU, 2 di/thread half2 =======================
__global__ void k_conv(const float* __restrict__ conv_w, const float* __restrict__ conv_b) {
    int idx = blockIdx.x * 256 + threadIdx.x;
    if (idx >= T_ * DI_ / 2) return;
    int dh = idx % (DI_ / 2);
    int t  = idx / (DI_ / 2);
    int di = dh * 2;
    int l  = t & (L_ - 1);
    float2 acc = make_float2(conv_b[di], conv_b[di + 1]);
    #pragma unroll
    for (int k = 0; k < KC_; k++) {
        int ll = l - (KC_ - 1) + k;
        if (ll >= 0) {
            float2 v = __half22float2(*(const __half2*)&g_xzh[(size_t)(t - (KC_ - 1) + k) * NI_ + di]);
            acc.x = fmaf(conv_w[di * KC_ + k],       v.x, acc.x);
            acc.y = fmaf(conv_w[(di + 1) * KC_ + k], v.y, acc.y);
        }
    }
    float sx = acc.x / (1.f + __expf(-acc.x));
    float sy = acc.y / (1.f + __expf(-acc.y));
    *(__half2*)&g_xch[(size_t)t * DI_ + di] = __floats2half2_rn(sx, sy);
}

// ======================= dt = softplus(dt_r @ W_dt + bias) -> half =======================
__global__ void k_dt(const float* __restrict__ W_dt, const float* __restrict__ dt_bias) {
    __shared__ float s_dtr[8][DTR_];
    int t0 = blockIdx.x * 8;
    int tid = threadIdx.x;
    if (tid < 8 * DTR_) {
        int tt = tid / DTR_, rr = tid % DTR_;
        s_dtr[tt][rr] = g_xdbl[(size_t)(t0 + tt) * XDN_ + rr];
    }
    __syncthreads();
    int di = tid;
    float bias = dt_bias[di];
    float acc[8];
    #pragma unroll
    for (int tt = 0; tt < 8; tt++) acc[tt] = bias;
    for (int rr = 0; rr < DTR_; rr++) {
        float w = W_dt[rr * DI_ + di];
        #pragma unroll
        for (int tt = 0; tt < 8; tt++) acc[tt] = fmaf(s_dtr[tt][rr], w, acc[tt]);
    }
    #pragma unroll
    for (int tt = 0; tt < 8; tt++) {
        float v = acc[tt];
        float sp = (v > 20.f) ? v : log1pf(__expf(v));
        g_dth[(size_t)(t0 + tt) * DI_ + di] = __float2half_rn(sp);
    }
}

// ======================= pack (B,C) interleaved =======================
__global__ void k_bcpack() {
    int idx = blockIdx.x * 256 + threadIdx.x;
    if (idx >= T_ * S_) return;
    int t = idx >> 4, s = idx & 15;
    float bv = g_xdbl[(size_t)t * XDN_ + DTR_ + s];
    float cv = g_xdbl[(size_t)t * XDN_ + DTR_ + S_ + s];
    ((float2*)g_bc)[idx] = make_float2(bv, cv);
}

// ======================= scan staging (shared by A and B passes) =======================
#define SCT_  32
#define SNCB_ (CL_ / SCT_)    // 32 chunks per L/4 segment
#define SST_  4

#define SCAN_STAGE(stv, t0v) do {                                              \
    {                                                                          \
        int tok = tid >> 1, q = tid & 1;                                       \
        cp_async16(st0 + (stv) * (SCT_ * 16 * 2) + tok * 32 + q * 16,          \
                   dtp + (size_t)((t0v) + tok) * DI_ + q * 8);                 \
        cp_async16(sx0 + (stv) * (SCT_ * 16 * 2) + tok * 32 + q * 16,          \
                   xcp + (size_t)((t0v) + tok) * DI_ + q * 8);                 \
    }                                                                          \
    _Pragma("unroll")                                                          \
    for (int i = 0; i < 4; i++) {                                              \
        int idx = tid + i * 64;                                                \
        int tok = idx >> 3, q = idx & 7;                                       \
        cp_async16(sb0 + (stv) * (SCT_ * 16 * 8) + tok * 128 + q * 16,         \
                   bcp + (size_t)((t0v) + tok) * S_ + q * 2);                  \
    }                                                                          \
} while (0)

// ======================= scan pass A: chunk-local end state + dA product =======================
__global__ void __launch_bounds__(64) k_scanA(const float* __restrict__ A_log) {
    __shared__ __half sdt[SST_][SCT_ * 16];
    __shared__ __half sxc[SST_][SCT_ * 16];
    __shared__ float2 sbc[SST_][SCT_ * 16];
    int dg = blockIdx.x, b = blockIdx.y, cz = blockIdx.z;   // cz in 0..2
    int tid = threadIdx.x;
    int di_l = tid >> 2, grp = tid & 3;
    int di = dg * 16 + di_l;
    float Ag[4], h[4] = {0.f, 0.f, 0.f, 0.f}, P[4] = {1.f, 1.f, 1.f, 1.f};
    #pragma unroll
    for (int j = 0; j < 4; j++)
        Ag[j] = -__expf(A_log[di * S_ + grp * 4 + j]) * 1.44269504f;
    size_t tbase = (size_t)b * L_ + (size_t)cz * CL_;
    const __half* dtp = g_dth + tbase * DI_ + dg * 16;
    const __half* xcp = g_xch + tbase * DI_ + dg * 16;
    const float2* bcp = (const float2*)g_bc + tbase * S_;

    uint32_t st0 = (uint32_t)__cvta_generic_to_shared(&sdt[0][0]);
    uint32_t sx0 = (uint32_t)__cvta_generic_to_shared(&sxc[0][0]);
    uint32_t sb0 = (uint32_t)__cvta_generic_to_shared(&sbc[0][0]);

    #pragma unroll
    for (int st = 0; st < SST_ - 1; st++) { SCAN_STAGE(st, st * SCT_); CP_COMMIT(); }

    for (int c = 0; c < SNCB_; c++) {
        CP_WAIT(2);
        __syncthreads();
        if (c + SST_ - 1 < SNCB_) {
            int st = (c + SST_ - 1) & (SST_ - 1);
            SCAN_STAGE(st, (c + SST_ - 1) * SCT_);
        }
        CP_COMMIT();

        const __half* pd = sdt[c & (SST_ - 1)];
        const __half* px = sxc[c & (SST_ - 1)];
        const float4* pb4 = (const float4*)sbc[c & (SST_ - 1)];
        #pragma unroll 8
        for (int j = 0; j < SCT_; j++) {
            float dtv = __half2float(pd[j * 16 + di_l]);
            float xv  = __half2float(px[j * 16 + di_l]);
            float4 q0 = pb4[j * 8 + grp * 2];
            float4 q1 = pb4[j * 8 + grp * 2 + 1];
            float dxx = dtv * xv;
            float dA0 = exp2f(dtv * Ag[0]);
            float dA1 = exp2f(dtv * Ag[1]);
            float dA2 = exp2f(dtv * Ag[2]);
            float dA3 = exp2f(dtv * Ag[3]);
            h[0] = fmaf(dA0, h[0], dxx * q0.x); P[0] *= dA0;
            h[1] = fmaf(dA1, h[1], dxx * q0.z); P[1] *= dA1;
            h[2] = fmaf(dA2, h[2], dxx * q1.x); P[2] *= dA2;
            h[3] = fmaf(dA3, h[3], dxx * q1.z); P[3] *= dA3;
        }
    }
    size_t f = ((size_t)(b * DI_ + di) * 16 + grp * 4);
    *(float4*)&g_se[(size_t)cz * NST_ + f] = make_float4(h[0], h[1], h[2], h[3]);
    *(float4*)&g_sp[(size_t)cz * NST_ + f] = make_float4(P[0], P[1], P[2], P[3]);
}

// ======================= scan fixup: chain chunk start states =======================
__global__ void k_scanF() {
    int i = blockIdx.x * 256 + threadIdx.x;   // NST_
    float hs1 = g_se[i];
    float hs2 = fmaf(g_sp[NST_ + i], hs1, g_se[NST_ + i]);
    float hs3 = fmaf(g_sp[2 * NST_ + i], hs2, g_se[2 * NST_ + i]);
    g_hs[i] = hs1;
    g_hs[NST_ + i] = hs2;
    g_hs[2 * NST_ + i] = hs3;
}

// ======================= scan pass B: full chunk scan with y output =======================
__global__ void __launch_bounds__(64) k_scanB(const float* __restrict__ A_log) {
    __shared__ __half sdt[SST_][SCT_ * 16];
    __shared__ __half sxc[SST_][SCT_ * 16];
    __shared__ float2 sbc[SST_][SCT_ * 16];
    int dg = blockIdx.x, b = blockIdx.y, cz = blockIdx.z;   // cz in 0..3
    int tid = threadIdx.x;
    int di_l = tid >> 2, grp = tid & 3;
    int di = dg * 16 + di_l;
    float Ag[4], h[4];
    #pragma unroll
    for (int j = 0; j < 4; j++)
        Ag[j] = -__expf(A_log[di * S_ + grp * 4 + j]) * 1.44269504f;
    size_t f = ((size_t)(b * DI_ + di) * 16 + grp * 4);
    if (cz == 0) { h[0] = h[1] = h[2] = h[3] = 0.f; }
    else {
        float4 v = *(const float4*)&g_hs[(size_t)(cz - 1) * NST_ + f];
        h[0] = v.x; h[1] = v.y; h[2] = v.z; h[3] = v.w;
    }
    size_t tbase = (size_t)b * L_ + (size_t)cz * CL_;
    const __half* dtp = g_dth + tbase * DI_ + dg * 16;
    const __half* xcp = g_xch + tbase * DI_ + dg * 16;
    const float2* bcp = (const float2*)g_bc + tbase * S_;

    uint32_t st0 = (uint32_t)__cvta_generic_to_shared(&sdt[0][0]);
    uint32_t sx0 = (uint32_t)__cvta_generic_to_shared(&sxc[0][0]);
    uint32_t sb0 = (uint32_t)__cvta_generic_to_shared(&sbc[0][0]);

    #pragma unroll
    for (int st = 0; st < SST_ - 1; st++) { SCAN_STAGE(st, st * SCT_); CP_COMMIT(); }

    for (int c = 0; c < SNCB_; c++) {
        CP_WAIT(2);
        __syncthreads();
        if (c + SST_ - 1 < SNCB_) {
            int st = (c + SST_ - 1) & (SST_ - 1);
            SCAN_STAGE(st, (c + SST_ - 1) * SCT_);
        }
        CP_COMMIT();

        const __half* pd = sdt[c & (SST_ - 1)];
        const __half* px = sxc[c & (SST_ - 1)];
        const float4* pb4 = (const float4*)sbc[c & (SST_ - 1)];
        size_t gy = (tbase + (size_t)c * SCT_) * DI_ + di;
        #pragma unroll 8
        for (int j = 0; j < SCT_; j++) {
            float dtv = __half2float(pd[j * 16 + di_l]);
            float xv  = __half2float(px[j * 16 + di_l]);
            float4 q0 = pb4[j * 8 + grp * 2];
            float4 q1 = pb4[j * 8 + grp * 2 + 1];
            float dxx = dtv * xv;
            float dA0 = exp2f(dtv * Ag[0]);
            float dA1 = exp2f(dtv * Ag[1]);
            float dA2 = exp2f(dtv * Ag[2]);
            float dA3 = exp2f(dtv * Ag[3]);
            h[0] = fmaf(dA0, h[0], dxx * q0.x);
            h[1] = fmaf(dA1, h[1], dxx * q0.z);
            h[2] = fmaf(dA2, h[2], dxx * q1.x);
            h[3] = fmaf(dA3, h[3], dxx * q1.z);
            float yp = h[0] * q0.y + h[1] * q0.w + h[2] * q1.y + h[3] * q1.w;
            yp += __shfl_xor_sync(0xffffffffu, yp, 1);
            yp += __shfl_xor_sync(0xffffffffu, yp, 2);
            if (grp == 0) g_yh[gy + (size_t)j * DI_] = __float2half_rn(yp);
        }
    }
}

// ======================= gate + Dskip + partial pool, 2 di/thread =======================
__global__ void k_ypart(const float* __restrict__ Dskip) {
    int dh    = blockIdx.x * 128 + threadIdx.x;
    int chunk = blockIdx.y;
    int b     = blockIdx.z;
    int di = dh * 2;
    float2 ds = *(const float2*)&Dskip[di];
    float2 acc = make_float2(0.f, 0.f);
    int t0 = b * L_ + chunk * 64;
    for (int i = 0; i < 64; i++) {
        int t = t0 + i;
        float2 z  = __half22float2(*(const __half2*)&g_xzh[(size_t)t * NI_ + DI_ + di]);
        float2 y  = __half22float2(*(const __half2*)&g_yh[(size_t)t * DI_ + di]);
        float2 xc = __half22float2(*(const __half2*)&g_xch[(size_t)t * DI_ + di]);
        float szx = z.x / (1.f + __expf(-z.x));
        float szy = z.y / (1.f + __expf(-z.y));
        acc.x = fmaf(y.x + xc.x * ds.x, szx, acc.x);
        acc.y = fmaf(y.y + xc.y * ds.y, szy, acc.y);
    }
    *(float2*)&g_ypart[(size_t)(chunk * B_ + b) * DI_ + di] = acc;
}
__global__ void k_ymean() {
    int i = blockIdx.x * 256 + threadIdx.x;
    float acc = 0.f;
    for (int c = 0; c < 64; c++) acc += g_ypart[(size_t)c * B_ * DI_ + i];
    g_ym[i] = acc * (1.f / L_);
}

// ======================= x-mean / pooled / head =======================
__global__ void k_xpart(const float* __restrict__ x) {
    int d = threadIdx.x;
    int chunk = blockIdx.x;
    int b = blockIdx.y;
    float acc = 0.f;
    int t0 = b * L_ + chunk * 64;
    for (int i = 0; i < 64; i++) acc += x[(size_t)(t0 + i) * D_ + d];
    g_xpart[(size_t)(chunk * B_ + b) * D_ + d] = acc;
}
__global__ void k_xmean() {
    int i = blockIdx.x * 256 + threadIdx.x;
    float acc = 0.f;
    for (int c = 0; c < 64; c++) acc += g_xpart[(size_t)c * B_ * D_ + i];
    g_xmean[i] = acc * (1.f / L_);
}
__global__ void k_pooled(const float* __restrict__ W_out) {
    int d = threadIdx.x;
    int b = blockIdx.x;
    float acc = g_xmean[b * D_ + d];
    for (int di = 0; di < DI_; di++)
        acc = fmaf(g_ym[b * DI_ + di], W_out[(size_t)di * D_ + d], acc);
    g_pooled[b * D_ + d] = acc;
}
__global__ void k_head(const float* __restrict__ W_fc, const float* __restrict__ b_fc,
                       const float* __restrict__ gamma, const float* __restrict__ beta,
                       const float* __restrict__ W_cls, const float* __restrict__ b_cls,
                       float* __restrict__ out) {
    __shared__ float sp[B_][D_];
    __shared__ float sh[B_][256];
    int tid = threadIdx.x;
    for (int i = tid; i < B_ * D_; i += 256) sp[i / D_][i % D_] = g_pooled[i];
    __syncthreads();
    int j = tid;
    float hv[B_];
    #pragma unroll
    for (int b = 0; b < B_; b++) hv[b] = b_fc[j];
    for (int k = 0; k < D_; k++) {
        float w = W_fc[(size_t)k * 256 + j];
        #pragma unroll
        for (int b = 0; b < B_; b++) hv[b] = fmaf(sp[b][k], w, hv[b]);
    }
    float mu = 0.f;
    #pragma unroll
    for (int b = 0; b < B_; b++) mu += hv[b];
    mu *= (1.f / B_);
    float var = 0.f;
    #pragma unroll
    for (int b = 0; b < B_; b++) { float dd = hv[b] - mu; var += dd * dd; }
    var *= (1.f / B_);
    float rs = rsqrtf(var + EPS_);
    float g = gamma[j], bt = beta[j];
    #pragma unroll
    for (int b = 0; b < B_; b++) {
        float v = (hv[b] - mu) * rs * g + bt;
        sh[b][j] = v > 0.f ? v : 0.f;
    }
    __syncthreads();
    for (int o = tid; o < B_ * NC_; o += 256) {
        int b = o / NC_, c = o % NC_;
        float acc = b_cls[c];
        for (int k = 0; k < 256; k++) acc = fmaf(sh[b][k], W_cls[k * NC_ + c], acc);
        out[o] = acc;
    }
}

// ======================= launch =======================
extern "C" void kernel_launch(void* const* d_in, const int* in_sizes, int n_in,
                              void* d_out, int out_size) {
    const float* x       = (const float*)d_in[0];
    const float* ln_w    = (const float*)d_in[1];
    const float* W_in    = (const float*)d_in[2];
    const float* conv_w  = (const float*)d_in[3];
    const float* conv_b  = (const float*)d_in[4];
    const float* W_xproj = (const float*)d_in[5];
    const float* W_dt    = (const float*)d_in[6];
    const float* dt_bias = (const float*)d_in[7];
    const float* A_log   = (const float*)d_in[8];
    const float* Dskip   = (const float*)d_in[9];
    const float* W_out   = (const float*)d_in[10];
    const float* W_fc    = (const float*)d_in[11];
    const float* b_fc    = (const float*)d_in[12];
    const float* bn_g    = (const float*)d_in[13];
    const float* bn_b    = (const float*)d_in[14];
    const float* W_cls   = (const float*)d_in[15];
    const float* b_cls   = (const float*)d_in[16];
    float* out = (float*)d_out;

    __half *p_xnh, *p_wth, *p_xzh, *p_xch;
    float *p_wt2, *p_xdbl;
    cudaGetSymbolAddress((void**)&p_xnh,  g_xnh);
    cudaGetSymbolAddress((void**)&p_wth,  g_wth);
    cudaGetSymbolAddress((void**)&p_xzh,  g_xzh);
    cudaGetSymbolAddress((void**)&p_xch,  g_xch);
    cudaGetSymbolAddress((void**)&p_wt2,  g_wt2);
    cudaGetSymbolAddress((void**)&p_xdbl, g_xdbl);

    static int s_attr_done = 0;
    if (!s_attr_done) {
        cudaFuncSetAttribute(k_gemm1, cudaFuncAttributeMaxDynamicSharedMemorySize, G1SM_);
        s_attr_done = 1;
    }

    // 1. RMSNorm (half out) + weight transposes
    k_rmsnorm<<<T_, 128>>>(x, ln_w);
    k_wt<<<dim3(D_ / 32, NI_ / 32), 256>>>(W_in);
    k_wt2<<<dim3(DI_ / 32, 2), 256>>>(W_xproj);
    // 2. xz = xn @ W_in — fp16 mma, ldmatrix, BK=64
    k_gemm1<<<dim3(NI_ / 128, T_ / 128), 256, G1SM_>>>(p_xnh, p_wth, p_xzh);
    // 3. conv + silu, 2 di/thread
    k_conv<<<(T_ * DI_ / 2 + 255) / 256, 256>>>(conv_w, conv_b);
    // 4. x_dbl = xc @ W_xproj — tf32 mma (half A)
    k_gemm2<<<T_ / 128, 256>>>(p_xch, p_wt2, p_xdbl);
    // 5. dt (half out) and BC pack
    k_dt<<<T_ / 8, DI_>>>(W_dt, dt_bias);
    k_bcpack<<<(T_ * S_ + 255) / 256, 256>>>();
    // 6. L-chunked scan: lean state pass + fixup + 4-way parallel full pass
    k_scanA<<<dim3(DI_ / 16, B_, NCHK_ - 1), 64>>>(A_log);
    k_scanF<<<NST_ / 256, 256>>>();
    k_scanB<<<dim3(DI_ / 16, B_, NCHK_), 64>>>(A_log);
    // 7. gate+pool + x-mean + pooled + head
    k_ypart<<<dim3(DI_ / 2 / 128, 64, B_), 128>>>(Dskip);
    k_ymean<<<(B_ * DI_) / 256, 256>>>();
    k_xpart<<<dim3(64, B_), D_>>>(x);
    k_xmean<<<(B_ * D_) / 256, 256>>>();
    k_pooled<<<B_, D_>>>(W_out);
    k_head<<<1, 256>>>(W_fc, b_fc, bn_g, bn_b, W_cls, b_cls, out);
}

// round 15
// speedup vs baseline: 1.0528x; 1.0528x over previous
#include <cuda_runtime.h>
#include <cuda_fp16.h>
#include <math.h>
#include <cstdint>

#define B_    8
#define L_    4096
#define D_    384
#define DI_   768
#define S_    16
#define DTR_  24
#define KC_   4
#define NC_   40
#define T_    (B_*L_)          // 32768 tokens
#define XDN_  (DTR_ + 2*S_)    // 56
#define NI_   (2*DI_)          // 1536
#define EPS_  1e-5f

// ======================= mma / async helpers =======================
__device__ __forceinline__ void mma_f16(float* c, const uint32_t* a, const uint32_t* b) {
    asm volatile(
        "mma.sync.aligned.m16n8k16.row.col.f32.f16.f16.f32 "
        "{%0,%1,%2,%3}, {%4,%5,%6,%7}, {%8,%9}, {%0,%1,%2,%3};\n"
        : "+f"(c[0]), "+f"(c[1]), "+f"(c[2]), "+f"(c[3])
        : "r"(a[0]), "r"(a[1]), "r"(a[2]), "r"(a[3]), "r"(b[0]), "r"(b[1]));
}
__device__ __forceinline__ void ldsm_x4(uint32_t& r0, uint32_t& r1, uint32_t& r2, uint32_t& r3,
                                        uint32_t addr) {
    asm volatile("ldmatrix.sync.aligned.m8n8.x4.shared.b16 {%0,%1,%2,%3}, [%4];"
        : "=r"(r0), "=r"(r1), "=r"(r2), "=r"(r3) : "r"(addr));
}
__device__ __forceinline__ void ldsm_x2(uint32_t& r0, uint32_t& r1, uint32_t addr) {
    asm volatile("ldmatrix.sync.aligned.m8n8.x2.shared.b16 {%0,%1}, [%2];"
        : "=r"(r0), "=r"(r1) : "r"(addr));
}
__device__ __forceinline__ void cp_async16(uint32_t saddr, const void* g) {
    asm volatile("cp.async.cg.shared.global [%0], [%1], 16;\n" :: "r"(saddr), "l"(g));
}
#define CP_COMMIT() asm volatile("cp.async.commit_group;\n" ::: "memory")
#define CP_WAIT(n)  asm volatile("cp.async.wait_group %0;\n" :: "n"(n) : "memory")

// ======================= scratch =======================
__device__ __align__(128) __half g_xnh [T_ * D_];        // rmsnorm output (half)
__device__ __align__(128) __half g_wth [NI_ * D_];       // W_in^T (half)
__device__ __align__(128) __half g_xzh [T_ * NI_];       // xn @ W_in (xp | z), HALF
__device__ __align__(128) __half g_xch [T_ * DI_];       // conv+silu output (half)
__device__ __align__(128) __half g_wt2h[64 * DI_];       // W_xproj^T zero-padded (half)
__device__ __align__(128) float  g_xdbl[T_ * XDN_];      // xc @ W_xproj
__device__ __align__(128) __half g_dth [T_ * DI_];       // softplus dt (half)
__device__ __align__(128) float  g_bc  [T_ * S_ * 2];    // (B, C) interleaved
__device__ __align__(128) __half g_yh  [T_ * DI_];       // scan output (half)
__device__ float g_ypart[64 * B_ * DI_];
__device__ float g_xpart[64 * B_ * D_];
__device__ float g_ym   [B_ * DI_];
__device__ float g_xmean[B_ * D_];
__device__ float g_pooled[B_ * D_];

// ======================= RMSNorm -> half =======================
__global__ void k_rmsnorm(const float* __restrict__ x, const float* __restrict__ ln_w) {
    int t = blockIdx.x;
    const float* xr = x + (size_t)t * D_;
    float ss = 0.f;
    for (int d = threadIdx.x; d < D_; d += 128) { float v = xr[d]; ss += v * v; }
    #pragma unroll
    for (int o = 16; o; o >>= 1) ss += __shfl_xor_sync(0xffffffffu, ss, o);
    __shared__ float sw[4];
    if ((threadIdx.x & 31) == 0) sw[threadIdx.x >> 5] = ss;
    __syncthreads();
    float tot = sw[0] + sw[1] + sw[2] + sw[3];
    float rs = rsqrtf(tot * (1.f / D_) + EPS_);
    for (int d = threadIdx.x; d < D_; d += 128)
        g_xnh[(size_t)t * D_ + d] = __float2half_rn(xr[d] * rs * ln_w[d]);
}

// ======================= W_in transpose -> half =======================
__global__ void k_wt(const float* __restrict__ W_in) {
    __shared__ float tile[32][33];
    int k0 = blockIdx.x * 32, n0 = blockIdx.y * 32;
    int tx = threadIdx.x & 31, ty = threadIdx.x >> 5;
    for (int i = 0; i < 32; i += 8)
        tile[ty + i][tx] = W_in[(size_t)(k0 + ty + i) * NI_ + n0 + tx];
    __syncthreads();
    for (int i = 0; i < 32; i += 8)
        g_wth[(size_t)(n0 + ty + i) * D_ + k0 + tx] = __float2half_rn(tile[tx][ty + i]);
}

// ======================= W_xproj transpose -> half, zero-padded to 64 rows =======================
__global__ void k_wt2(const float* __restrict__ W) {
    __shared__ float tile[32][33];
    int k0 = blockIdx.x * 32, n0 = blockIdx.y * 32;
    int tx = threadIdx.x & 31, ty = threadIdx.x >> 5;
    for (int i = 0; i < 32; i += 8)
        tile[ty + i][tx] = (n0 + tx < XDN_) ? W[(size_t)(k0 + ty + i) * XDN_ + n0 + tx] : 0.f;
    __syncthreads();
    for (int i = 0; i < 32; i += 8)
        g_wt2h[(size_t)(n0 + ty + i) * DI_ + k0 + tx] = __float2half_rn(tile[tx][ty + i]);
}

// ======================= GEMM1: fp16 mma + cp.async 2-stage, BK=64, ldmatrix =====
#define G1P_   72
#define G1ST_  (128 * G1P_ * 2)
#define G1SM_  (4 * G1ST_)

__global__ void __launch_bounds__(256, 2) k_gemm1(const __half* __restrict__ A,
                                                  const __half* __restrict__ Bt,
                                                  __half* __restrict__ C) {
    extern __shared__ __half g1s[];
    int tid = threadIdx.x;
    int lane = tid & 31, wid = tid >> 5;
    int wm = wid >> 2, wn = wid & 3;
    int gid = lane >> 2, tig = lane & 3;
    int m0 = blockIdx.y * 128, n0 = blockIdx.x * 128;

    uint32_t sa0 = (uint32_t)__cvta_generic_to_shared(&g1s[0]);
    uint32_t sb0 = sa0 + 2 * G1ST_;

    int a_row = ((lane >> 3) & 1) * 8 + (lane & 7);
    int a_kof = (lane >> 4) * 8;
    int b_row = lane & 7;
    int b_kof = ((lane >> 3) & 1) * 8;

    float acc[4][4][4];
    #pragma unroll
    for (int i = 0; i < 4; i++)
        #pragma unroll
        for (int j = 0; j < 4; j++)
            #pragma unroll
            for (int q = 0; q < 4; q++) acc[i][j][q] = 0.f;

    #pragma unroll
    for (int i = 0; i < 4; i++) {
        int f = tid + i * 256;
        int row = f >> 3, c8 = f & 7;
        cp_async16(sa0 + row * (G1P_ * 2) + c8 * 16,
                   &A[(size_t)(m0 + row) * D_ + c8 * 8]);
        cp_async16(sb0 + row * (G1P_ * 2) + c8 * 16,
                   &Bt[(size_t)(n0 + row) * D_ + c8 * 8]);
    }
    CP_COMMIT();

    for (int c = 0; c < 6; c++) {
        int cur = c & 1;
        if (c < 5) {
            int nxt = (c + 1) & 1;
            #pragma unroll
            for (int i = 0; i < 4; i++) {
                int f = tid + i * 256;
                int row = f >> 3, c8 = f & 7;
                cp_async16(sa0 + nxt * G1ST_ + row * (G1P_ * 2) + c8 * 16,
                           &A[(size_t)(m0 + row) * D_ + (c + 1) * 64 + c8 * 8]);
                cp_async16(sb0 + nxt * G1ST_ + row * (G1P_ * 2) + c8 * 16,
                           &Bt[(size_t)(n0 + row) * D_ + (c + 1) * 64 + c8 * 8]);
            }
            CP_COMMIT();
            CP_WAIT(1);
        } else {
            CP_WAIT(0);
        }
        __syncthreads();
        uint32_t pa = sa0 + cur * G1ST_;
        uint32_t pb = sb0 + cur * G1ST_;
        #pragma unroll
        for (int kk = 0; kk < 64; kk += 16) {
            uint32_t af[4][4], bf[4][2];
            #pragma unroll
            for (int mt = 0; mt < 4; mt++) {
                int r = wm * 64 + mt * 16 + a_row;
                ldsm_x4(af[mt][0], af[mt][1], af[mt][2], af[mt][3],
                        pa + r * (G1P_ * 2) + (kk + a_kof) * 2);
            }
            #pragma unroll
            for (int nt = 0; nt < 4; nt++) {
                int r = wn * 32 + nt * 8 + b_row;
                ldsm_x2(bf[nt][0], bf[nt][1],
                        pb + r * (G1P_ * 2) + (kk + b_kof) * 2);
            }
            #pragma unroll
            for (int mt = 0; mt < 4; mt++)
                #pragma unroll
                for (int nt = 0; nt < 4; nt++)
                    mma_f16(acc[mt][nt], af[mt], bf[nt]);
        }
        __syncthreads();
    }
    #pragma unroll
    for (int mt = 0; mt < 4; mt++) {
        int row = m0 + wm * 64 + mt * 16 + gid;
        #pragma unroll
        for (int nt = 0; nt < 4; nt++) {
            int col = n0 + wn * 32 + nt * 8 + 2 * tig;
            *(__half2*)&C[(size_t)row * NI_ + col] =
                __floats2half2_rn(acc[mt][nt][0], acc[mt][nt][1]);
            *(__half2*)&C[(size_t)(row + 8) * NI_ + col] =
                __floats2half2_rn(acc[mt][nt][2], acc[mt][nt][3]);
        }
    }
}

// ======================= GEMM2: fp16 mma, x_dbl[T,56] = xc(half) @ W_xproj(half) ==========
// Tile M=128, N=64, BK=64. 256 threads, 8 warps (4x2), warp tile 32x32.
#define G2P_ 72

__global__ void __launch_bounds__(256, 2) k_gemm2(const __half* __restrict__ A,
                                                  const __half* __restrict__ Bt,
                                                  float* __restrict__ C) {
    __shared__ __half sA[128 * G2P_];
    __shared__ __half sB[64 * G2P_];
    int tid = threadIdx.x;
    int lane = tid & 31, wid = tid >> 5;
    int wm = wid >> 1, wn = wid & 1;
    int gid = lane >> 2, tig = lane & 3;
    int m0 = blockIdx.x * 128;

    uint32_t sa0 = (uint32_t)__cvta_generic_to_shared(&sA[0]);
    uint32_t sb0 = (uint32_t)__cvta_generic_to_shared(&sB[0]);

    int a_row = ((lane >> 3) & 1) * 8 + (lane & 7);
    int a_kof = (lane >> 4) * 8;
    int b_row = lane & 7;
    int b_kof = ((lane >> 3) & 1) * 8;

    float acc[2][4][4];
    #pragma unroll
    for (int i = 0; i < 2; i++)
        #pragma unroll
        for (int j = 0; j < 4; j++)
            #pragma unroll
            for (int q = 0; q < 4; q++) acc[i][j][q] = 0.f;

    for (int c = 0; c < 12; c++) {
        #pragma unroll
        for (int i = 0; i < 4; i++) {
            int f = tid + i * 256;
            int row = f >> 3, c8 = f & 7;
            cp_async16(sa0 + row * (G2P_ * 2) + c8 * 16,
                       &A[(size_t)(m0 + row) * DI_ + c * 64 + c8 * 8]);
        }
        #pragma unroll
        for (int i = 0; i < 2; i++) {
            int f = tid + i * 256;
            int row = f >> 3, c8 = f & 7;
            cp_async16(sb0 + row * (G2P_ * 2) + c8 * 16,
                       &Bt[(size_t)row * DI_ + c * 64 + c8 * 8]);
        }
        CP_COMMIT();
        CP_WAIT(0);
        __syncthreads();
        #pragma unroll
        for (int kk = 0; kk < 64; kk += 16) {
            uint32_t af[2][4], bf[4][2];
            #pragma unroll
            for (int mt = 0; mt < 2; mt++) {
                int r = wm * 32 + mt * 16 + a_row;
                ldsm_x4(af[mt][0], af[mt][1], af[mt][2], af[mt][3],
                        sa0 + r * (G2P_ * 2) + (kk + a_kof) * 2);
            }
            #pragma unroll
            for (int nt = 0; nt < 4; nt++) {
                int r = wn * 32 + nt * 8 + b_row;
                ldsm_x2(bf[nt][0], bf[nt][1],
                        sb0 + r * (G2P_ * 2) + (kk + b_kof) * 2);
            }
            #pragma unroll
            for (int mt = 0; mt < 2; mt++)
                #pragma unroll
                for (int nt = 0; nt < 4; nt++)
                    mma_f16(acc[mt][nt], af[mt], bf[nt]);
        }
        __syncthreads();
    }
    #pragma unroll
    for (int mt = 0; mt < 2; mt++) {
        int row = m0 + wm * 32 + mt * 16 + gid;
        #pragma unroll
        for (int nt = 0; nt < 4; nt++) {
            int col = wn * 32 + nt * 8 + 2 * tig;
            if (col < XDN_) {
                *(float2*)&C[(size_t)row * XDN_ + col]       = make_float2(acc[mt][nt][0], acc[mt][nt][1]);
                *(float2*)&C[(size_t)(row + 8) * XDN_ + col] = make_float2(acc[mt][nt][2], acc[mt][nt][3]);
            }
        }
    }
}

// ======================= conv (K=4) + SiLU, 2 di/thread half2 =======================
__global__ void k_conv(const float* __restrict__ conv_w, const float* __restrict__ conv_b) {
    int idx = blockIdx.x * 256 + threadIdx.x;
    if (idx >= T_ * DI_ / 2) return;
    int dh = idx % (DI_ / 2);
    int t  = idx / (DI_ / 2);
    int di = dh * 2;
    int l  = t & (L_ - 1);
    float2 acc = make_float2(conv_b[di], conv_b[di + 1]);
    #pragma unroll
    for (int k = 0; k < KC_; k++) {
        int ll = l - (KC_ - 1) + k;
        if (ll >= 0) {
            float2 v = __half22float2(*(const __half2*)&g_xzh[(size_t)(t - (KC_ - 1) + k) * NI_ + di]);
            acc.x = fmaf(conv_w[di * KC_ + k],       v.x, acc.x);
            acc.y = fmaf(conv_w[(di + 1) * KC_ + k], v.y, acc.y);
        }
    }
    float sx = acc.x / (1.f + __expf(-acc.x));
    float sy = acc.y / (1.f + __expf(-acc.y));
    *(__half2*)&g_xch[(size_t)t * DI_ + di] = __floats2half2_rn(sx, sy);
}

// ======================= dt = softplus(dt_r @ W_dt + bias) -> half, 16 tokens/block ==========
__global__ void k_dt(const float* __restrict__ W_dt, const float* __restrict__ dt_bias) {
    __shared__ float s_dtr[16][DTR_];
    int t0 = blockIdx.x * 16;
    int tid = threadIdx.x;
    if (tid < 16 * DTR_) {
        int tt = tid / DTR_, rr = tid % DTR_;
        s_dtr[tt][rr] = g_xdbl[(size_t)(t0 + tt) * XDN_ + rr];
    }
    __syncthreads();
    int di = tid;
    float bias = dt_bias[di];
    float acc[16];
    #pragma unroll
    for (int tt = 0; tt < 16; tt++) acc[tt] = bias;
    for (int rr = 0; rr < DTR_; rr++) {
        float w = W_dt[rr * DI_ + di];
        #pragma unroll
        for (int tt = 0; tt < 16; tt++) acc[tt] = fmaf(s_dtr[tt][rr], w, acc[tt]);
    }
    #pragma unroll
    for (int tt = 0; tt < 16; tt++) {
        float v = acc[tt];
        float sp = (v > 20.f) ? v : log1pf(__expf(v));
        g_dth[(size_t)(t0 + tt) * DI_ + di] = __float2half_rn(sp);
    }
}

// ======================= pack (B,C) interleaved =======================
__global__ void k_bcpack() {
    int idx = blockIdx.x * 256 + threadIdx.x;
    if (idx >= T_ * S_) return;
    int t = idx >> 4, s = idx & 15;
    float bv = g_xdbl[(size_t)t * XDN_ + DTR_ + s];
    float cv = g_xdbl[(size_t)t * XDN_ + DTR_ + S_ + s];
    ((float2*)g_bc)[idx] = make_float2(bv, cv);
}

// ======================= selective scan — R13 exact (cp.async pipeline, 4 states/thread) ======
#define SCT_  32
#define SNC_  (L_ / SCT_)
#define SST_  4

__global__ void __launch_bounds__(64) k_scan2(const float* __restrict__ A_log) {
    __shared__ __half sdt[SST_][SCT_ * 16];
    __shared__ __half sxc[SST_][SCT_ * 16];
    __shared__ float2 sbc[SST_][SCT_ * 16];
    int dg = blockIdx.x, b = blockIdx.y;
    int tid = threadIdx.x;
    int di_l = tid >> 2;
    int grp  = tid & 3;
    int di = dg * 16 + di_l;
    float Ag[4], h[4] = {0.f, 0.f, 0.f, 0.f};
    #pragma unroll
    for (int j = 0; j < 4; j++)
        Ag[j] = -__expf(A_log[di * S_ + grp * 4 + j]) * 1.44269504f;
    size_t tbase = (size_t)b * L_;
    const __half* dtp = g_dth + tbase * DI_ + dg * 16;
    const __half* xcp = g_xch + tbase * DI_ + dg * 16;
    const float2* bc  = (const float2*)g_bc + tbase * S_;

    uint32_t st0 = (uint32_t)__cvta_generic_to_shared(&sdt[0][0]);
    uint32_t sx0 = (uint32_t)__cvta_generic_to_shared(&sxc[0][0]);
    uint32_t sb0 = (uint32_t)__cvta_generic_to_shared(&sbc[0][0]);

    #pragma unroll
    for (int st = 0; st < SST_ - 1; st++) {
        int t0 = st * SCT_;
        {
            int tok = tid >> 1, q = tid & 1;
            cp_async16(st0 + st * (SCT_ * 16 * 2) + tok * 32 + q * 16,
                       dtp + (size_t)(t0 + tok) * DI_ + q * 8);
            cp_async16(sx0 + st * (SCT_ * 16 * 2) + tok * 32 + q * 16,
                       xcp + (size_t)(t0 + tok) * DI_ + q * 8);
        }
        #pragma unroll
        for (int i = 0; i < 4; i++) {
            int idx = tid + i * 64;
            int tok = idx >> 3, q = idx & 7;
            cp_async16(sb0 + st * (SCT_ * 16 * 8) + tok * 128 + q * 16,
                       bc + (size_t)(t0 + tok) * S_ + q * 2);
        }
        CP_COMMIT();
    }

    for (int c = 0; c < SNC_; c++) {
        CP_WAIT(2);
        __syncthreads();
        if (c + SST_ - 1 < SNC_) {
            int st = (c + SST_ - 1) & (SST_ - 1);
            int t0 = (c + SST_ - 1) * SCT_;
            {
                int tok = tid >> 1, q = tid & 1;
                cp_async16(st0 + st * (SCT_ * 16 * 2) + tok * 32 + q * 16,
                           dtp + (size_t)(t0 + tok) * DI_ + q * 8);
                cp_async16(sx0 + st * (SCT_ * 16 * 2) + tok * 32 + q * 16,
                           xcp + (size_t)(t0 + tok) * DI_ + q * 8);
            }
            #pragma unroll
            for (int i = 0; i < 4; i++) {
                int idx = tid + i * 64;
                int tok = idx >> 3, q = idx & 7;
                cp_async16(sb0 + st * (SCT_ * 16 * 8) + tok * 128 + q * 16,
                           bc + (size_t)(t0 + tok) * S_ + q * 2);
            }
        }
        CP_COMMIT();

        const __half* pd = sdt[c & (SST_ - 1)];
        const __half* px = sxc[c & (SST_ - 1)];
        const float4* pb4 = (const float4*)sbc[c & (SST_ - 1)];
        size_t gy = (tbase + (size_t)c * SCT_) * DI_ + di;
        #pragma unroll 8
        for (int j = 0; j < SCT_; j++) {
            float dtv = __half2float(pd[j * 16 + di_l]);
            float xv  = __half2float(px[j * 16 + di_l]);
            float4 q0 = pb4[j * 8 + grp * 2];
            float4 q1 = pb4[j * 8 + grp * 2 + 1];
            float dxx = dtv * xv;
            float dA0 = exp2f(dtv * Ag[0]);
            float dA1 = exp2f(dtv * Ag[1]);
            float dA2 = exp2f(dtv * Ag[2]);
            float dA3 = exp2f(dtv * Ag[3]);
            h[0] = fmaf(dA0, h[0], dxx * q0.x);
            h[1] = fmaf(dA1, h[1], dxx * q0.z);
            h[2] = fmaf(dA2, h[2], dxx * q1.x);
            h[3] = fmaf(dA3, h[3], dxx * q1.z);
            float yp = h[0] * q0.y + h[1] * q0.w + h[2] * q1.y + h[3] * q1.w;
            yp += __shfl_xor_sync(0xffffffffu, yp, 1);
            yp += __shfl_xor_sync(0xffffffffu, yp, 2);
            if (grp == 0) g_yh[gy + (size_t)j * DI_] = __float2half_rn(yp);
        }
    }
}

// ======================= gate + Dskip + partial pool, 2 di/thread =======================
__global__ void k_ypart(const float* __restrict__ Dskip) {
    int dh    = blockIdx.x * 128 + threadIdx.x;
    int chunk = blockIdx.y;
    int b     = blockIdx.z;
    int di = dh * 2;
    float2 ds = *(const float2*)&Dskip[di];
    float2 acc = make_float2(0.f, 0.f);
    int t0 = b * L_ + chunk * 64;
    for (int i = 0; i < 64; i++) {
        int t = t0 + i;
        float2 z  = __half22float2(*(const __half2*)&g_xzh[(size_t)t * NI_ + DI_ + di]);
        float2 y  = __half22float2(*(const __half2*)&g_yh[(size_t)t * DI_ + di]);
        float2 xc = __half22float2(*(const __half2*)&g_xch[(size_t)t * DI_ + di]);
        float szx = z.x / (1.f + __expf(-z.x));
        float szy = z.y / (1.f + __expf(-z.y));
        acc.x = fmaf(y.x + xc.x * ds.x, szx, acc.x);
        acc.y = fmaf(y.y + xc.y * ds.y, szy, acc.y);
    }
    *(float2*)&g_ypart[(size_t)(chunk * B_ + b) * DI_ + di] = acc;
}
__global__ void k_ymean() {
    int i = blockIdx.x * 256 + threadIdx.x;
    float acc = 0.f;
    for (int c = 0; c < 64; c++) acc += g_ypart[(size_t)c * B_ * DI_ + i];
    g_ym[i] = acc * (1.f / L_);
}

// ======================= x-mean / pooled / head =======================
__global__ void k_xpart(const float* __restrict__ x) {
    int d = threadIdx.x;
    int chunk = blockIdx.x;
    int b = blockIdx.y;
    float acc = 0.f;
    int t0 = b * L_ + chunk * 64;
    for (int i = 0; i < 64; i++) acc += x[(size_t)(t0 + i) * D_ + d];
    g_xpart[(size_t)(chunk * B_ + b) * D_ + d] = acc;
}
__global__ void k_xmean() {
    int i = blockIdx.x * 256 + threadIdx.x;
    float acc = 0.f;
    for (int c = 0; c < 64; c++) acc += g_xpart[(size_t)c * B_ * D_ + i];
    g_xmean[i] = acc * (1.f / L_);
}
__global__ void k_pooled(const float* __restrict__ W_out) {
    int d = threadIdx.x;
    int b = blockIdx.x;
    float acc = g_xmean[b * D_ + d];
    for (int di = 0; di < DI_; di++)
        acc = fmaf(g_ym[b * DI_ + di], W_out[(size_t)di * D_ + d], acc);
    g_pooled[b * D_ + d] = acc;
}
__global__ void k_head(const float* __restrict__ W_fc, const float* __restrict__ b_fc,
                       const float* __restrict__ gamma, const float* __restrict__ beta,
                       const float* __restrict__ W_cls, const float* __restrict__ b_cls,
                       float* __restrict__ out) {
    __shared__ float sp[B_][D_];
    __shared__ float sh[B_][256];
    int tid = threadIdx.x;
    for (int i = tid; i < B_ * D_; i += 256) sp[i / D_][i % D_] = g_pooled[i];
    __syncthreads();
    int j = tid;
    float hv[B_];
    #pragma unroll
    for (int b = 0; b < B_; b++) hv[b] = b_fc[j];
    for (int k = 0; k < D_; k++) {
        float w = W_fc[(size_t)k * 256 + j];
        #pragma unroll
        for (int b = 0; b < B_; b++) hv[b] = fmaf(sp[b][k], w, hv[b]);
    }
    float mu = 0.f;
    #pragma unroll
    for (int b = 0; b < B_; b++) mu += hv[b];
    mu *= (1.f / B_);
    float var = 0.f;
    #pragma unroll
    for (int b = 0; b < B_; b++) { float dd = hv[b] - mu; var += dd * dd; }
    var *= (1.f / B_);
    float rs = rsqrtf(var + EPS_);
    float g = gamma[j], bt = beta[j];
    #pragma unroll
    for (int b = 0; b < B_; b++) {
        float v = (hv[b] - mu) * rs * g + bt;
        sh[b][j] = v > 0.f ? v : 0.f;
    }
    __syncthreads();
    for (int o = tid; o < B_ * NC_; o += 256) {
        int b = o / NC_, c = o % NC_;
        float acc = b_cls[c];
        for (int k = 0; k < 256; k++) acc = fmaf(sh[b][k], W_cls[k * NC_ + c], acc);
        out[o] = acc;
    }
}

// ======================= launch =======================
extern "C" void kernel_launch(void* const* d_in, const int* in_sizes, int n_in,
                              void* d_out, int out_size) {
    const float* x       = (const float*)d_in[0];
    const float* ln_w    = (const float*)d_in[1];
    const float* W_in    = (const float*)d_in[2];
    const float* conv_w  = (const float*)d_in[3];
    const float* conv_b  = (const float*)d_in[4];
    const float* W_xproj = (const float*)d_in[5];
    const float* W_dt    = (const float*)d_in[6];
    const float* dt_bias = (const float*)d_in[7];
    const float* A_log   = (const float*)d_in[8];
    const float* Dskip   = (const float*)d_in[9];
    const float* W_out   = (const float*)d_in[10];
    const float* W_fc    = (const float*)d_in[11];
    const float* b_fc    = (const float*)d_in[12];
    const float* bn_g    = (const float*)d_in[13];
    const float* bn_b    = (const float*)d_in[14];
    const float* W_cls   = (const float*)d_in[15];
    const float* b_cls   = (const float*)d_in[16];
    float* out = (float*)d_out;

    __half *p_xnh, *p_wth, *p_xzh, *p_xch, *p_wt2h;
    cudaGetSymbolAddress((void**)&p_xnh,  g_xnh);
    cudaGetSymbolAddress((void**)&p_wth,  g_wth);
    cudaGetSymbolAddress((void**)&p_xzh,  g_xzh);
    cudaGetSymbolAddress((void**)&p_xch,  g_xch);
    cudaGetSymbolAddress((void**)&p_wt2h, g_wt2h);
    float* p_xdbl;
    cudaGetSymbolAddress((void**)&p_xdbl, g_xdbl);

    static int s_attr_done = 0;
    if (!s_attr_done) {
        cudaFuncSetAttribute(k_gemm1, cudaFuncAttributeMaxDynamicSharedMemorySize, G1SM_);
        s_attr_done = 1;
    }

    // 1. RMSNorm (half out) + weight transposes
    k_rmsnorm<<<T_, 128>>>(x, ln_w);
    k_wt<<<dim3(D_ / 32, NI_ / 32), 256>>>(W_in);
    k_wt2<<<dim3(DI_ / 32, 2), 256>>>(W_xproj);
    // 2. xz = xn @ W_in — fp16 mma, ldmatrix, BK=64
    k_gemm1<<<dim3(NI_ / 128, T_ / 128), 256, G1SM_>>>(p_xnh, p_wth, p_xzh);
    // 3. conv + silu, 2 di/thread
    k_conv<<<(T_ * DI_ / 2 + 255) / 256, 256>>>(conv_w, conv_b);
    // 4. x_dbl = xc @ W_xproj — fp16 mma
    k_gemm2<<<T_ / 128, 256>>>(p_xch, p_wt2h, p_xdbl);
    // 5. dt (16 tokens/block, half out) and BC pack
    k_dt<<<T_ / 16, DI_>>>(W_dt, dt_bias);
    k_bcpack<<<(T_ * S_ + 255) / 256, 256>>>();
    // 6. selective scan — R13 single-pass (verified-fast)
    k_scan2<<<dim3(DI_ / 16, B_), 64>>>(A_log);
    // 7. gate+pool + x-mean + pooled + head
    k_ypart<<<dim3(DI_ / 2 / 128, 64, B_), 128>>>(Dskip);
    k_ymean<<<(B_ * DI_) / 256, 256>>>();
    k_xpart<<<dim3(64, B_), D_>>>(x);
    k_xmean<<<(B_ * D_) / 256, 256>>>();
    k_pooled<<<B_, D_>>>(W_out);
    k_head<<<1, 256>>>(W_fc, b_fc, bn_g, bn_b, W_cls, b_cls, out);
}

// round 16
// speedup vs baseline: 1.0719x; 1.0181x over previous
#include <cuda_runtime.h>
#include <cuda_fp16.h>
#include <math.h>
#include <cstdint>

#define B_    8
#define L_    4096
#define D_    384
#define DI_   768
#define S_    16
#define DTR_  24
#define KC_   4
#define NC_   40
#define T_    (B_*L_)          // 32768 tokens
#define XDN_  (DTR_ + 2*S_)    // 56
#define NI_   (2*DI_)          // 1536
#define EPS_  1e-5f

// ======================= mma / async helpers =======================
__device__ __forceinline__ void mma_f16(float* c, const uint32_t* a, const uint32_t* b) {
    asm volatile(
        "mma.sync.aligned.m16n8k16.row.col.f32.f16.f16.f32 "
        "{%0,%1,%2,%3}, {%4,%5,%6,%7}, {%8,%9}, {%0,%1,%2,%3};\n"
        : "+f"(c[0]), "+f"(c[1]), "+f"(c[2]), "+f"(c[3])
        : "r"(a[0]), "r"(a[1]), "r"(a[2]), "r"(a[3]), "r"(b[0]), "r"(b[1]));
}
__device__ __forceinline__ void ldsm_x4(uint32_t& r0, uint32_t& r1, uint32_t& r2, uint32_t& r3,
                                        uint32_t addr) {
    asm volatile("ldmatrix.sync.aligned.m8n8.x4.shared.b16 {%0,%1,%2,%3}, [%4];"
        : "=r"(r0), "=r"(r1), "=r"(r2), "=r"(r3) : "r"(addr));
}
__device__ __forceinline__ void cp_async16(uint32_t saddr, const void* g) {
    asm volatile("cp.async.cg.shared.global [%0], [%1], 16;\n" :: "r"(saddr), "l"(g));
}
#define CP_COMMIT() asm volatile("cp.async.commit_group;\n" ::: "memory")
#define CP_WAIT(n)  asm volatile("cp.async.wait_group %0;\n" :: "n"(n) : "memory")

// ======================= scratch =======================
__device__ __align__(128) __half g_xnh [T_ * D_];        // rmsnorm output (half)
__device__ __align__(128) __half g_wth [NI_ * D_];       // W_in^T (half)
__device__ __align__(128) __half g_xzh [T_ * NI_];       // xn @ W_in (xp | z), HALF
__device__ __align__(128) __half g_xch [T_ * DI_];       // conv+silu output (half)
__device__ __align__(128) __half g_wt2h[64 * DI_];       // W_xproj^T zero-padded (half)
__device__ __align__(128) float  g_xdbl[T_ * XDN_];      // dt_r columns only
__device__ __align__(128) __half g_dth [T_ * DI_];       // softplus dt (half)
__device__ __align__(128) float  g_bc  [T_ * S_ * 2];    // (B, C) interleaved
__device__ __align__(128) __half g_yh  [T_ * DI_];       // scan output (half)
__device__ float g_ypart[64 * B_ * DI_];
__device__ float g_xpart[64 * B_ * D_];
__device__ float g_ym   [B_ * DI_];
__device__ float g_xmean[B_ * D_];
__device__ float g_pooled[B_ * D_];

// ======================= RMSNorm -> half =======================
__global__ void k_rmsnorm(const float* __restrict__ x, const float* __restrict__ ln_w) {
    int t = blockIdx.x;
    const float* xr = x + (size_t)t * D_;
    float ss = 0.f;
    for (int d = threadIdx.x; d < D_; d += 128) { float v = xr[d]; ss += v * v; }
    #pragma unroll
    for (int o = 16; o; o >>= 1) ss += __shfl_xor_sync(0xffffffffu, ss, o);
    __shared__ float sw[4];
    if ((threadIdx.x & 31) == 0) sw[threadIdx.x >> 5] = ss;
    __syncthreads();
    float tot = sw[0] + sw[1] + sw[2] + sw[3];
    float rs = rsqrtf(tot * (1.f / D_) + EPS_);
    for (int d = threadIdx.x; d < D_; d += 128)
        g_xnh[(size_t)t * D_ + d] = __float2half_rn(xr[d] * rs * ln_w[d]);
}

// ======================= W_in transpose -> half =======================
__global__ void k_wt(const float* __restrict__ W_in) {
    __shared__ float tile[32][33];
    int k0 = blockIdx.x * 32, n0 = blockIdx.y * 32;
    int tx = threadIdx.x & 31, ty = threadIdx.x >> 5;
    for (int i = 0; i < 32; i += 8)
        tile[ty + i][tx] = W_in[(size_t)(k0 + ty + i) * NI_ + n0 + tx];
    __syncthreads();
    for (int i = 0; i < 32; i += 8)
        g_wth[(size_t)(n0 + ty + i) * D_ + k0 + tx] = __float2half_rn(tile[tx][ty + i]);
}

// ======================= W_xproj transpose -> half, zero-padded to 64 rows =======================
__global__ void k_wt2(const float* __restrict__ W) {
    __shared__ float tile[32][33];
    int k0 = blockIdx.x * 32, n0 = blockIdx.y * 32;
    int tx = threadIdx.x & 31, ty = threadIdx.x >> 5;
    for (int i = 0; i < 32; i += 8)
        tile[ty + i][tx] = (n0 + tx < XDN_) ? W[(size_t)(k0 + ty + i) * XDN_ + n0 + tx] : 0.f;
    __syncthreads();
    for (int i = 0; i < 32; i += 8)
        g_wt2h[(size_t)(n0 + ty + i) * DI_ + k0 + tx] = __float2half_rn(tile[tx][ty + i]);
}

// ======================= GEMM1: fp16 mma + cp.async 2-stage, BK=64, ldmatrix x4 =====
#define G1P_   72
#define G1ST_  (128 * G1P_ * 2)
#define G1SM_  (4 * G1ST_)

__global__ void __launch_bounds__(256, 2) k_gemm1(const __half* __restrict__ A,
                                                  const __half* __restrict__ Bt,
                                                  __half* __restrict__ C) {
    extern __shared__ __half g1s[];
    int tid = threadIdx.x;
    int lane = tid & 31, wid = tid >> 5;
    int wm = wid >> 2, wn = wid & 3;
    int gid = lane >> 2, tig = lane & 3;
    int m0 = blockIdx.y * 128, n0 = blockIdx.x * 128;

    uint32_t sa0 = (uint32_t)__cvta_generic_to_shared(&g1s[0]);
    uint32_t sb0 = sa0 + 2 * G1ST_;

    int a_row = ((lane >> 3) & 1) * 8 + (lane & 7);   // A: row<-bit3, k<-bit4
    int a_kof = (lane >> 4) * 8;
    int b2_row = ((lane >> 4) & 1) * 8 + (lane & 7);  // B pair-x4: row<-bit4, k<-bit3
    int b2_kof = ((lane >> 3) & 1) * 8;

    float acc[4][4][4];
    #pragma unroll
    for (int i = 0; i < 4; i++)
        #pragma unroll
        for (int j = 0; j < 4; j++)
            #pragma unroll
            for (int q = 0; q < 4; q++) acc[i][j][q] = 0.f;

    #pragma unroll
    for (int i = 0; i < 4; i++) {
        int f = tid + i * 256;
        int row = f >> 3, c8 = f & 7;
        cp_async16(sa0 + row * (G1P_ * 2) + c8 * 16,
                   &A[(size_t)(m0 + row) * D_ + c8 * 8]);
        cp_async16(sb0 + row * (G1P_ * 2) + c8 * 16,
                   &Bt[(size_t)(n0 + row) * D_ + c8 * 8]);
    }
    CP_COMMIT();

    for (int c = 0; c < 6; c++) {
        int cur = c & 1;
        if (c < 5) {
            int nxt = (c + 1) & 1;
            #pragma unroll
            for (int i = 0; i < 4; i++) {
                int f = tid + i * 256;
                int row = f >> 3, c8 = f & 7;
                cp_async16(sa0 + nxt * G1ST_ + row * (G1P_ * 2) + c8 * 16,
                           &A[(size_t)(m0 + row) * D_ + (c + 1) * 64 + c8 * 8]);
                cp_async16(sb0 + nxt * G1ST_ + row * (G1P_ * 2) + c8 * 16,
                           &Bt[(size_t)(n0 + row) * D_ + (c + 1) * 64 + c8 * 8]);
            }
            CP_COMMIT();
            CP_WAIT(1);
        } else {
            CP_WAIT(0);
        }
        __syncthreads();
        uint32_t pa = sa0 + cur * G1ST_;
        uint32_t pb = sb0 + cur * G1ST_;
        #pragma unroll
        for (int kk = 0; kk < 64; kk += 16) {
            uint32_t af[4][4], bf[4][2];
            #pragma unroll
            for (int mt = 0; mt < 4; mt++) {
                int r = wm * 64 + mt * 16 + a_row;
                ldsm_x4(af[mt][0], af[mt][1], af[mt][2], af[mt][3],
                        pa + r * (G1P_ * 2) + (kk + a_kof) * 2);
            }
            #pragma unroll
            for (int p = 0; p < 2; p++) {
                int r = wn * 32 + p * 16 + b2_row;
                ldsm_x4(bf[2 * p][0], bf[2 * p][1], bf[2 * p + 1][0], bf[2 * p + 1][1],
                        pb + r * (G1P_ * 2) + (kk + b2_kof) * 2);
            }
            #pragma unroll
            for (int mt = 0; mt < 4; mt++)
                #pragma unroll
                for (int nt = 0; nt < 4; nt++)
                    mma_f16(acc[mt][nt], af[mt], bf[nt]);
        }
        __syncthreads();
    }
    #pragma unroll
    for (int mt = 0; mt < 4; mt++) {
        int row = m0 + wm * 64 + mt * 16 + gid;
        #pragma unroll
        for (int nt = 0; nt < 4; nt++) {
            int col = n0 + wn * 32 + nt * 8 + 2 * tig;
            *(__half2*)&C[(size_t)row * NI_ + col] =
                __floats2half2_rn(acc[mt][nt][0], acc[mt][nt][1]);
            *(__half2*)&C[(size_t)(row + 8) * NI_ + col] =
                __floats2half2_rn(acc[mt][nt][2], acc[mt][nt][3]);
        }
    }
}

// ======================= GEMM2: fp16 mma, 2-stage, fused bc scatter =======================
// Tile M=128, N=64, BK=64, 256 threads, 8 warps (4x2), warp tile 32x32.
#define G2P_   72
#define G2AST_ (128 * G2P_ * 2)   // A stage bytes (18432)
#define G2BST_ (64 * G2P_ * 2)    // B stage bytes (9216)
#define G2SM_  (2 * G2AST_ + 2 * G2BST_)  // 55296

__device__ __forceinline__ void g2_store(int row, int col, float v, float* __restrict__ xdbl) {
    if (col < DTR_) xdbl[(size_t)row * XDN_ + col] = v;
    else if (col < DTR_ + S_)  g_bc[((size_t)row * S_ + (col - DTR_)) * 2]       = v;
    else if (col < XDN_)       g_bc[((size_t)row * S_ + (col - DTR_ - S_)) * 2 + 1] = v;
}

__global__ void __launch_bounds__(256, 2) k_gemm2(const __half* __restrict__ A,
                                                  const __half* __restrict__ Bt,
                                                  float* __restrict__ C) {
    extern __shared__ __half g2s[];
    int tid = threadIdx.x;
    int lane = tid & 31, wid = tid >> 5;
    int wm = wid >> 1, wn = wid & 1;
    int gid = lane >> 2, tig = lane & 3;
    int m0 = blockIdx.x * 128;

    uint32_t sa0 = (uint32_t)__cvta_generic_to_shared(&g2s[0]);
    uint32_t sb0 = sa0 + 2 * G2AST_;

    int a_row = ((lane >> 3) & 1) * 8 + (lane & 7);
    int a_kof = (lane >> 4) * 8;
    int b2_row = ((lane >> 4) & 1) * 8 + (lane & 7);
    int b2_kof = ((lane >> 3) & 1) * 8;

    float acc[2][4][4];
    #pragma unroll
    for (int i = 0; i < 2; i++)
        #pragma unroll
        for (int j = 0; j < 4; j++)
            #pragma unroll
            for (int q = 0; q < 4; q++) acc[i][j][q] = 0.f;

    // prologue: chunk 0
    #pragma unroll
    for (int i = 0; i < 4; i++) {
        int f = tid + i * 256;
        int row = f >> 3, c8 = f & 7;
        cp_async16(sa0 + row * (G2P_ * 2) + c8 * 16,
                   &A[(size_t)(m0 + row) * DI_ + c8 * 8]);
    }
    #pragma unroll
    for (int i = 0; i < 2; i++) {
        int f = tid + i * 256;
        int row = f >> 3, c8 = f & 7;
        cp_async16(sb0 + row * (G2P_ * 2) + c8 * 16,
                   &Bt[(size_t)row * DI_ + c8 * 8]);
    }
    CP_COMMIT();

    for (int c = 0; c < 12; c++) {
        int cur = c & 1;
        if (c < 11) {
            int nxt = (c + 1) & 1;
            #pragma unroll
            for (int i = 0; i < 4; i++) {
                int f = tid + i * 256;
                int row = f >> 3, c8 = f & 7;
                cp_async16(sa0 + nxt * G2AST_ + row * (G2P_ * 2) + c8 * 16,
                           &A[(size_t)(m0 + row) * DI_ + (c + 1) * 64 + c8 * 8]);
            }
            #pragma unroll
            for (int i = 0; i < 2; i++) {
                int f = tid + i * 256;
                int row = f >> 3, c8 = f & 7;
                cp_async16(sb0 + nxt * G2BST_ + row * (G2P_ * 2) + c8 * 16,
                           &Bt[(size_t)row * DI_ + (c + 1) * 64 + c8 * 8]);
            }
            CP_COMMIT();
            CP_WAIT(1);
        } else {
            CP_WAIT(0);
        }
        __syncthreads();
        uint32_t pa = sa0 + cur * G2AST_;
        uint32_t pb = sb0 + cur * G2BST_;
        #pragma unroll
        for (int kk = 0; kk < 64; kk += 16) {
            uint32_t af[2][4], bf[4][2];
            #pragma unroll
            for (int mt = 0; mt < 2; mt++) {
                int r = wm * 32 + mt * 16 + a_row;
                ldsm_x4(af[mt][0], af[mt][1], af[mt][2], af[mt][3],
                        pa + r * (G2P_ * 2) + (kk + a_kof) * 2);
            }
            #pragma unroll
            for (int p = 0; p < 2; p++) {
                int r = wn * 32 + p * 16 + b2_row;
                ldsm_x4(bf[2 * p][0], bf[2 * p][1], bf[2 * p + 1][0], bf[2 * p + 1][1],
                        pb + r * (G2P_ * 2) + (kk + b2_kof) * 2);
            }
            #pragma unroll
            for (int mt = 0; mt < 2; mt++)
                #pragma unroll
                for (int nt = 0; nt < 4; nt++)
                    mma_f16(acc[mt][nt], af[mt], bf[nt]);
        }
        __syncthreads();
    }
    #pragma unroll
    for (int mt = 0; mt < 2; mt++) {
        int row = m0 + wm * 32 + mt * 16 + gid;
        #pragma unroll
        for (int nt = 0; nt < 4; nt++) {
            int col = wn * 32 + nt * 8 + 2 * tig;
            g2_store(row,     col,     acc[mt][nt][0], C);
            g2_store(row,     col + 1, acc[mt][nt][1], C);
            g2_store(row + 8, col,     acc[mt][nt][2], C);
            g2_store(row + 8, col + 1, acc[mt][nt][3], C);
        }
    }
}

// ======================= conv (K=4) + SiLU, 2 di/thread half2 =======================
__global__ void k_conv(const float* __restrict__ conv_w, const float* __restrict__ conv_b) {
    int idx = blockIdx.x * 256 + threadIdx.x;
    if (idx >= T_ * DI_ / 2) return;
    int dh = idx % (DI_ / 2);
    int t  = idx / (DI_ / 2);
    int di = dh * 2;
    int l  = t & (L_ - 1);
    float2 acc = make_float2(conv_b[di], conv_b[di + 1]);
    #pragma unroll
    for (int k = 0; k < KC_; k++) {
        int ll = l - (KC_ - 1) + k;
        if (ll >= 0) {
            float2 v = __half22float2(*(const __half2*)&g_xzh[(size_t)(t - (KC_ - 1) + k) * NI_ + di]);
            acc.x = fmaf(conv_w[di * KC_ + k],       v.x, acc.x);
            acc.y = fmaf(conv_w[(di + 1) * KC_ + k], v.y, acc.y);
        }
    }
    float sx = acc.x / (1.f + __expf(-acc.x));
    float sy = acc.y / (1.f + __expf(-acc.y));
    *(__half2*)&g_xch[(size_t)t * DI_ + di] = __floats2half2_rn(sx, sy);
}

// ======================= dt = softplus(dt_r @ W_dt + bias) -> half, 16 tokens/block ==========
__global__ void k_dt(const float* __restrict__ W_dt, const float* __restrict__ dt_bias) {
    __shared__ float s_dtr[16][DTR_];
    int t0 = blockIdx.x * 16;
    int tid = threadIdx.x;
    if (tid < 16 * DTR_) {
        int tt = tid / DTR_, rr = tid % DTR_;
        s_dtr[tt][rr] = g_xdbl[(size_t)(t0 + tt) * XDN_ + rr];
    }
    __syncthreads();
    int di = tid;
    float bias = dt_bias[di];
    float acc[16];
    #pragma unroll
    for (int tt = 0; tt < 16; tt++) acc[tt] = bias;
    for (int rr = 0; rr < DTR_; rr++) {
        float w = W_dt[rr * DI_ + di];
        #pragma unroll
        for (int tt = 0; tt < 16; tt++) acc[tt] = fmaf(s_dtr[tt][rr], w, acc[tt]);
    }
    #pragma unroll
    for (int tt = 0; tt < 16; tt++) {
        float v = acc[tt];
        float sp = (v > 20.f) ? v : log1pf(__expf(v));
        g_dth[(size_t)(t0 + tt) * DI_ + di] = __float2half_rn(sp);
    }
}

// ======================= selective scan — R13 exact (cp.async pipeline, 4 states/thread) ======
#define SCT_  32
#define SNC_  (L_ / SCT_)
#define SST_  4

__global__ void __launch_bounds__(64) k_scan2(const float* __restrict__ A_log) {
    __shared__ __half sdt[SST_][SCT_ * 16];
    __shared__ __half sxc[SST_][SCT_ * 16];
    __shared__ float2 sbc[SST_][SCT_ * 16];
    int dg = blockIdx.x, b = blockIdx.y;
    int tid = threadIdx.x;
    int di_l = tid >> 2;
    int grp  = tid & 3;
    int di = dg * 16 + di_l;
    float Ag[4], h[4] = {0.f, 0.f, 0.f, 0.f};
    #pragma unroll
    for (int j = 0; j < 4; j++)
        Ag[j] = -__expf(A_log[di * S_ + grp * 4 + j]) * 1.44269504f;
    size_t tbase = (size_t)b * L_;
    const __half* dtp = g_dth + tbase * DI_ + dg * 16;
    const __half* xcp = g_xch + tbase * DI_ + dg * 16;
    const float2* bc  = (const float2*)g_bc + tbase * S_;

    uint32_t st0 = (uint32_t)__cvta_generic_to_shared(&sdt[0][0]);
    uint32_t sx0 = (uint32_t)__cvta_generic_to_shared(&sxc[0][0]);
    uint32_t sb0 = (uint32_t)__cvta_generic_to_shared(&sbc[0][0]);

    #pragma unroll
    for (int st = 0; st < SST_ - 1; st++) {
        int t0 = st * SCT_;
        {
            int tok = tid >> 1, q = tid & 1;
            cp_async16(st0 + st * (SCT_ * 16 * 2) + tok * 32 + q * 16,
                       dtp + (size_t)(t0 + tok) * DI_ + q * 8);
            cp_async16(sx0 + st * (SCT_ * 16 * 2) + tok * 32 + q * 16,
                       xcp + (size_t)(t0 + tok) * DI_ + q * 8);
        }
        #pragma unroll
        for (int i = 0; i < 4; i++) {
            int idx = tid + i * 64;
            int tok = idx >> 3, q = idx & 7;
            cp_async16(sb0 + st * (SCT_ * 16 * 8) + tok * 128 + q * 16,
                       bc + (size_t)(t0 + tok) * S_ + q * 2);
        }
        CP_COMMIT();
    }

    for (int c = 0; c < SNC_; c++) {
        CP_WAIT(2);
        __syncthreads();
        if (c + SST_ - 1 < SNC_) {
            int st = (c + SST_ - 1) & (SST_ - 1);
            int t0 = (c + SST_ - 1) * SCT_;
            {
                int tok = tid >> 1, q = tid & 1;
                cp_async16(st0 + st * (SCT_ * 16 * 2) + tok * 32 + q * 16,
                           dtp + (size_t)(t0 + tok) * DI_ + q * 8);
                cp_async16(sx0 + st * (SCT_ * 16 * 2) + tok * 32 + q * 16,
                           xcp + (size_t)(t0 + tok) * DI_ + q * 8);
            }
            #pragma unroll
            for (int i = 0; i < 4; i++) {
                int idx = tid + i * 64;
                int tok = idx >> 3, q = idx & 7;
                cp_async16(sb0 + st * (SCT_ * 16 * 8) + tok * 128 + q * 16,
                           bc + (size_t)(t0 + tok) * S_ + q * 2);
            }
        }
        CP_COMMIT();

        const __half* pd = sdt[c & (SST_ - 1)];
        const __half* px = sxc[c & (SST_ - 1)];
        const float4* pb4 = (const float4*)sbc[c & (SST_ - 1)];
        size_t gy = (tbase + (size_t)c * SCT_) * DI_ + di;
        #pragma unroll 8
        for (int j = 0; j < SCT_; j++) {
            float dtv = __half2float(pd[j * 16 + di_l]);
            float xv  = __half2float(px[j * 16 + di_l]);
            float4 q0 = pb4[j * 8 + grp * 2];
            float4 q1 = pb4[j * 8 + grp * 2 + 1];
            float dxx = dtv * xv;
            float dA0 = exp2f(dtv * Ag[0]);
            float dA1 = exp2f(dtv * Ag[1]);
            float dA2 = exp2f(dtv * Ag[2]);
            float dA3 = exp2f(dtv * Ag[3]);
            h[0] = fmaf(dA0, h[0], dxx * q0.x);
            h[1] = fmaf(dA1, h[1], dxx * q0.z);
            h[2] = fmaf(dA2, h[2], dxx * q1.x);
            h[3] = fmaf(dA3, h[3], dxx * q1.z);
            float yp = h[0] * q0.y + h[1] * q0.w + h[2] * q1.y + h[3] * q1.w;
            yp += __shfl_xor_sync(0xffffffffu, yp, 1);
            yp += __shfl_xor_sync(0xffffffffu, yp, 2);
            if (grp == 0) g_yh[gy + (size_t)j * DI_] = __float2half_rn(yp);
        }
    }
}

// ======================= gate + Dskip + partial pool, 2 di/thread =======================
__global__ void k_ypart(const float* __restrict__ Dskip) {
    int dh    = blockIdx.x * 128 + threadIdx.x;
    int chunk = blockIdx.y;
    int b     = blockIdx.z;
    int di = dh * 2;
    float2 ds = *(const float2*)&Dskip[di];
    float2 acc = make_float2(0.f, 0.f);
    int t0 = b * L_ + chunk * 64;
    for (int i = 0; i < 64; i++) {
        int t = t0 + i;
        float2 z  = __half22float2(*(const __half2*)&g_xzh[(size_t)t * NI_ + DI_ + di]);
        float2 y  = __half22float2(*(const __half2*)&g_yh[(size_t)t * DI_ + di]);
        float2 xc = __half22float2(*(const __half2*)&g_xch[(size_t)t * DI_ + di]);
        float szx = z.x / (1.f + __expf(-z.x));
        float szy = z.y / (1.f + __expf(-z.y));
        acc.x = fmaf(y.x + xc.x * ds.x, szx, acc.x);
        acc.y = fmaf(y.y + xc.y * ds.y, szy, acc.y);
    }
    *(float2*)&g_ypart[(size_t)(chunk * B_ + b) * DI_ + di] = acc;
}
__global__ void k_ymean() {
    int i = blockIdx.x * 256 + threadIdx.x;
    float acc = 0.f;
    for (int c = 0; c < 64; c++) acc += g_ypart[(size_t)c * B_ * DI_ + i];
    g_ym[i] = acc * (1.f / L_);
}

// ======================= x-mean / pooled / head =======================
__global__ void k_xpart(const float* __restrict__ x) {
    int d = threadIdx.x;
    int chunk = blockIdx.x;
    int b = blockIdx.y;
    float acc = 0.f;
    int t0 = b * L_ + chunk * 64;
    for (int i = 0; i < 64; i++) acc += x[(size_t)(t0 + i) * D_ + d];
    g_xpart[(size_t)(chunk * B_ + b) * D_ + d] = acc;
}
__global__ void k_xmean() {
    int i = blockIdx.x * 256 + threadIdx.x;
    float acc = 0.f;
    for (int c = 0; c < 64; c++) acc += g_xpart[(size_t)c * B_ * D_ + i];
    g_xmean[i] = acc * (1.f / L_);
}
__global__ void k_pooled(const float* __restrict__ W_out) {
    int d = threadIdx.x;
    int b = blockIdx.x;
    float acc = g_xmean[b * D_ + d];
    for (int di = 0; di < DI_; di++)
        acc = fmaf(g_ym[b * DI_ + di], W_out[(size_t)di * D_ + d], acc);
    g_pooled[b * D_ + d] = acc;
}
__global__ void k_head(const float* __restrict__ W_fc, const float* __restrict__ b_fc,
                       const float* __restrict__ gamma, const float* __restrict__ beta,
                       const float* __restrict__ W_cls, const float* __restrict__ b_cls,
                       float* __restrict__ out) {
    __shared__ float sp[B_][D_];
    __shared__ float sh[B_][256];
    int tid = threadIdx.x;
    for (int i = tid; i < B_ * D_; i += 256) sp[i / D_][i % D_] = g_pooled[i];
    __syncthreads();
    int j = tid;
    float hv[B_];
    #pragma unroll
    for (int b = 0; b < B_; b++) hv[b] = b_fc[j];
    for (int k = 0; k < D_; k++) {
        float w = W_fc[(size_t)k * 256 + j];
        #pragma unroll
        for (int b = 0; b < B_; b++) hv[b] = fmaf(sp[b][k], w, hv[b]);
    }
    float mu = 0.f;
    #pragma unroll
    for (int b = 0; b < B_; b++) mu += hv[b];
    mu *= (1.f / B_);
    float var = 0.f;
    #pragma unroll
    for (int b = 0; b < B_; b++) { float dd = hv[b] - mu; var += dd * dd; }
    var *= (1.f / B_);
    float rs = rsqrtf(var + EPS_);
    float g = gamma[j], bt = beta[j];
    #pragma unroll
    for (int b = 0; b < B_; b++) {
        float v = (hv[b] - mu) * rs * g + bt;
        sh[b][j] = v > 0.f ? v : 0.f;
    }
    __syncthreads();
    for (int o = tid; o < B_ * NC_; o += 256) {
        int b = o / NC_, c = o % NC_;
        float acc = b_cls[c];
        for (int k = 0; k < 256; k++) acc = fmaf(sh[b][k], W_cls[k * NC_ + c], acc);
        out[o] = acc;
    }
}

// ======================= launch =======================
extern "C" void kernel_launch(void* const* d_in, const int* in_sizes, int n_in,
                              void* d_out, int out_size) {
    const float* x       = (const float*)d_in[0];
    const float* ln_w    = (const float*)d_in[1];
    const float* W_in    = (const float*)d_in[2];
    const float* conv_w  = (const float*)d_in[3];
    const float* conv_b  = (const float*)d_in[4];
    const float* W_xproj = (const float*)d_in[5];
    const float* W_dt    = (const float*)d_in[6];
    const float* dt_bias = (const float*)d_in[7];
    const float* A_log   = (const float*)d_in[8];
    const float* Dskip   = (const float*)d_in[9];
    const float* W_out   = (const float*)d_in[10];
    const float* W_fc    = (const float*)d_in[11];
    const float* b_fc    = (const float*)d_in[12];
    const float* bn_g    = (const float*)d_in[13];
    const float* bn_b    = (const float*)d_in[14];
    const float* W_cls   = (const float*)d_in[15];
    const float* b_cls   = (const float*)d_in[16];
    float* out = (float*)d_out;

    __half *p_xnh, *p_wth, *p_xzh, *p_xch, *p_wt2h;
    cudaGetSymbolAddress((void**)&p_xnh,  g_xnh);
    cudaGetSymbolAddress((void**)&p_wth,  g_wth);
    cudaGetSymbolAddress((void**)&p_xzh,  g_xzh);
    cudaGetSymbolAddress((void**)&p_xch,  g_xch);
    cudaGetSymbolAddress((void**)&p_wt2h, g_wt2h);
    float* p_xdbl;
    cudaGetSymbolAddress((void**)&p_xdbl, g_xdbl);

    static int s_attr_done = 0;
    if (!s_attr_done) {
        cudaFuncSetAttribute(k_gemm1, cudaFuncAttributeMaxDynamicSharedMemorySize, G1SM_);
        cudaFuncSetAttribute(k_gemm2, cudaFuncAttributeMaxDynamicSharedMemorySize, G2SM_);
        s_attr_done = 1;
    }

    // 1. RMSNorm (half out) + weight transposes
    k_rmsnorm<<<T_, 128>>>(x, ln_w);
    k_wt<<<dim3(D_ / 32, NI_ / 32), 256>>>(W_in);
    k_wt2<<<dim3(DI_ / 32, 2), 256>>>(W_xproj);
    // 2. xz = xn @ W_in — fp16 mma, ldmatrix x4, BK=64
    k_gemm1<<<dim3(NI_ / 128, T_ / 128), 256, G1SM_>>>(p_xnh, p_wth, p_xzh);
    // 3. conv + silu, 2 di/thread
    k_conv<<<(T_ * DI_ / 2 + 255) / 256, 256>>>(conv_w, conv_b);
    // 4. x_dbl = xc @ W_xproj — fp16 mma, 2-stage pipeline, fused bc scatter
    k_gemm2<<<T_ / 128, 256, G2SM_>>>(p_xch, p_wt2h, p_xdbl);
    // 5. dt (16 tokens/block, half out)
    k_dt<<<T_ / 16, DI_>>>(W_dt, dt_bias);
    // 6. selective scan — single-pass (verified-fast)
    k_scan2<<<dim3(DI_ / 16, B_), 64>>>(A_log);
    // 7. gate+pool + x-mean + pooled + head
    k_ypart<<<dim3(DI_ / 2 / 128, 64, B_), 128>>>(Dskip);
    k_ymean<<<(B_ * DI_) / 256, 256>>>();
    k_xpart<<<dim3(64, B_), D_>>>(x);
    k_xmean<<<(B_ * D_) / 256, 256>>>();
    k_pooled<<<B_, D_>>>(W_out);
    k_head<<<1, 256>>>(W_fc, b_fc, bn_g, bn_b, W_cls, b_cls, out);
}

// round 17
// speedup vs baseline: 1.1832x; 1.1038x over previous
#include <cuda_runtime.h>
#include <cuda_fp16.h>
#include <math.h>
#include <cstdint>

#define B_    8
#define L_    4096
#define D_    384
#define DI_   768
#define S_    16
#define DTR_  24
#define KC_   4
#define NC_   40
#define T_    (B_*L_)          // 32768 tokens
#define XDN_  (DTR_ + 2*S_)    // 56
#define NI_   (2*DI_)          // 1536
#define EPS_  1e-5f

// ======================= mma / async helpers =======================
__device__ __forceinline__ void mma_f16(float* c, const uint32_t* a, const uint32_t* b) {
    asm volatile(
        "mma.sync.aligned.m16n8k16.row.col.f32.f16.f16.f32 "
        "{%0,%1,%2,%3}, {%4,%5,%6,%7}, {%8,%9}, {%0,%1,%2,%3};\n"
        : "+f"(c[0]), "+f"(c[1]), "+f"(c[2]), "+f"(c[3])
        : "r"(a[0]), "r"(a[1]), "r"(a[2]), "r"(a[3]), "r"(b[0]), "r"(b[1]));
}
__device__ __forceinline__ void ldsm_x4(uint32_t& r0, uint32_t& r1, uint32_t& r2, uint32_t& r3,
                                        uint32_t addr) {
    asm volatile("ldmatrix.sync.aligned.m8n8.x4.shared.b16 {%0,%1,%2,%3}, [%4];"
        : "=r"(r0), "=r"(r1), "=r"(r2), "=r"(r3) : "r"(addr));
}
__device__ __forceinline__ void cp_async16(uint32_t saddr, const void* g) {
    asm volatile("cp.async.cg.shared.global [%0], [%1], 16;\n" :: "r"(saddr), "l"(g));
}
#define CP_COMMIT() asm volatile("cp.async.commit_group;\n" ::: "memory")
#define CP_WAIT(n)  asm volatile("cp.async.wait_group %0;\n" :: "n"(n) : "memory")

// ======================= scratch =======================
__device__ __align__(128) __half g_xnh [T_ * D_];        // rmsnorm output (half)
__device__ __align__(128) __half g_wth [NI_ * D_];       // W_in^T (half)
__device__ __align__(128) __half g_xzh [T_ * NI_];       // xn @ W_in (xp | z), HALF
__device__ __align__(128) __half g_xch [T_ * DI_];       // conv+silu output (half)
__device__ __align__(128) __half g_wt2h[64 * DI_];       // W_xproj^T zero-padded (half)
__device__ __align__(128) float  g_xdbl[T_ * XDN_];      // dt_r columns only
__device__ __align__(128) __half g_dth [T_ * DI_];       // softplus dt (half)
__device__ __align__(128) float  g_bc  [T_ * S_ * 2];    // (B, C) interleaved
__device__ __align__(128) __half g_yh  [T_ * DI_];       // scan output (half)
__device__ float g_ypart[64 * B_ * DI_];
__device__ float g_xpart[64 * B_ * D_];
__device__ float g_ym   [B_ * DI_];
__device__ float g_xmean[B_ * D_];
__device__ float g_pooled[B_ * D_];

// ======================= RMSNorm -> half =======================
__global__ void k_rmsnorm(const float* __restrict__ x, const float* __restrict__ ln_w) {
    int t = blockIdx.x;
    const float* xr = x + (size_t)t * D_;
    float ss = 0.f;
    for (int d = threadIdx.x; d < D_; d += 128) { float v = xr[d]; ss += v * v; }
    #pragma unroll
    for (int o = 16; o; o >>= 1) ss += __shfl_xor_sync(0xffffffffu, ss, o);
    __shared__ float sw[4];
    if ((threadIdx.x & 31) == 0) sw[threadIdx.x >> 5] = ss;
    __syncthreads();
    float tot = sw[0] + sw[1] + sw[2] + sw[3];
    float rs = rsqrtf(tot * (1.f / D_) + EPS_);
    for (int d = threadIdx.x; d < D_; d += 128)
        g_xnh[(size_t)t * D_ + d] = __float2half_rn(xr[d] * rs * ln_w[d]);
}

// ======================= W_in transpose -> half =======================
__global__ void k_wt(const float* __restrict__ W_in) {
    __shared__ float tile[32][33];
    int k0 = blockIdx.x * 32, n0 = blockIdx.y * 32;
    int tx = threadIdx.x & 31, ty = threadIdx.x >> 5;
    for (int i = 0; i < 32; i += 8)
        tile[ty + i][tx] = W_in[(size_t)(k0 + ty + i) * NI_ + n0 + tx];
    __syncthreads();
    for (int i = 0; i < 32; i += 8)
        g_wth[(size_t)(n0 + ty + i) * D_ + k0 + tx] = __float2half_rn(tile[tx][ty + i]);
}

// ======================= W_xproj transpose -> half, zero-padded to 64 rows =======================
__global__ void k_wt2(const float* __restrict__ W) {
    __shared__ float tile[32][33];
    int k0 = blockIdx.x * 32, n0 = blockIdx.y * 32;
    int tx = threadIdx.x & 31, ty = threadIdx.x >> 5;
    for (int i = 0; i < 32; i += 8)
        tile[ty + i][tx] = (n0 + tx < XDN_) ? W[(size_t)(k0 + ty + i) * XDN_ + n0 + tx] : 0.f;
    __syncthreads();
    for (int i = 0; i < 32; i += 8)
        g_wt2h[(size_t)(n0 + ty + i) * DI_ + k0 + tx] = __float2half_rn(tile[tx][ty + i]);
}

// ======================= GEMM1: fp16 mma + cp.async 2-stage, BK=64, ldmatrix x4 =====
#define G1P_   72
#define G1ST_  (128 * G1P_ * 2)
#define G1SM_  (4 * G1ST_)

__global__ void __launch_bounds__(256, 2) k_gemm1(const __half* __restrict__ A,
                                                  const __half* __restrict__ Bt,
                                                  __half* __restrict__ C) {
    extern __shared__ __half g1s[];
    int tid = threadIdx.x;
    int lane = tid & 31, wid = tid >> 5;
    int wm = wid >> 2, wn = wid & 3;
    int gid = lane >> 2, tig = lane & 3;
    int m0 = blockIdx.y * 128, n0 = blockIdx.x * 128;

    uint32_t sa0 = (uint32_t)__cvta_generic_to_shared(&g1s[0]);
    uint32_t sb0 = sa0 + 2 * G1ST_;

    int a_row = ((lane >> 3) & 1) * 8 + (lane & 7);
    int a_kof = (lane >> 4) * 8;
    int b2_row = ((lane >> 4) & 1) * 8 + (lane & 7);
    int b2_kof = ((lane >> 3) & 1) * 8;

    float acc[4][4][4];
    #pragma unroll
    for (int i = 0; i < 4; i++)
        #pragma unroll
        for (int j = 0; j < 4; j++)
            #pragma unroll
            for (int q = 0; q < 4; q++) acc[i][j][q] = 0.f;

    #pragma unroll
    for (int i = 0; i < 4; i++) {
        int f = tid + i * 256;
        int row = f >> 3, c8 = f & 7;
        cp_async16(sa0 + row * (G1P_ * 2) + c8 * 16,
                   &A[(size_t)(m0 + row) * D_ + c8 * 8]);
        cp_async16(sb0 + row * (G1P_ * 2) + c8 * 16,
                   &Bt[(size_t)(n0 + row) * D_ + c8 * 8]);
    }
    CP_COMMIT();

    for (int c = 0; c < 6; c++) {
        int cur = c & 1;
        if (c < 5) {
            int nxt = (c + 1) & 1;
            #pragma unroll
            for (int i = 0; i < 4; i++) {
                int f = tid + i * 256;
                int row = f >> 3, c8 = f & 7;
                cp_async16(sa0 + nxt * G1ST_ + row * (G1P_ * 2) + c8 * 16,
                           &A[(size_t)(m0 + row) * D_ + (c + 1) * 64 + c8 * 8]);
                cp_async16(sb0 + nxt * G1ST_ + row * (G1P_ * 2) + c8 * 16,
                           &Bt[(size_t)(n0 + row) * D_ + (c + 1) * 64 + c8 * 8]);
            }
            CP_COMMIT();
            CP_WAIT(1);
        } else {
            CP_WAIT(0);
        }
        __syncthreads();
        uint32_t pa = sa0 + cur * G1ST_;
        uint32_t pb = sb0 + cur * G1ST_;
        #pragma unroll
        for (int kk = 0; kk < 64; kk += 16) {
            uint32_t af[4][4], bf[4][2];
            #pragma unroll
            for (int mt = 0; mt < 4; mt++) {
                int r = wm * 64 + mt * 16 + a_row;
                ldsm_x4(af[mt][0], af[mt][1], af[mt][2], af[mt][3],
                        pa + r * (G1P_ * 2) + (kk + a_kof) * 2);
            }
            #pragma unroll
            for (int p = 0; p < 2; p++) {
                int r = wn * 32 + p * 16 + b2_row;
                ldsm_x4(bf[2 * p][0], bf[2 * p][1], bf[2 * p + 1][0], bf[2 * p + 1][1],
                        pb + r * (G1P_ * 2) + (kk + b2_kof) * 2);
            }
            #pragma unroll
            for (int mt = 0; mt < 4; mt++)
                #pragma unroll
                for (int nt = 0; nt < 4; nt++)
                    mma_f16(acc[mt][nt], af[mt], bf[nt]);
        }
        __syncthreads();
    }
    #pragma unroll
    for (int mt = 0; mt < 4; mt++) {
        int row = m0 + wm * 64 + mt * 16 + gid;
        #pragma unroll
        for (int nt = 0; nt < 4; nt++) {
            int col = n0 + wn * 32 + nt * 8 + 2 * tig;
            *(__half2*)&C[(size_t)row * NI_ + col] =
                __floats2half2_rn(acc[mt][nt][0], acc[mt][nt][1]);
            *(__half2*)&C[(size_t)(row + 8) * NI_ + col] =
                __floats2half2_rn(acc[mt][nt][2], acc[mt][nt][3]);
        }
    }
}

// ======================= GEMM2: fp16 mma, 2-stage, fused bc scatter =======================
#define G2P_   72
#define G2AST_ (128 * G2P_ * 2)
#define G2BST_ (64 * G2P_ * 2)
#define G2SM_  (2 * G2AST_ + 2 * G2BST_)

__device__ __forceinline__ void g2_store(int row, int col, float v, float* __restrict__ xdbl) {
    if (col < DTR_) xdbl[(size_t)row * XDN_ + col] = v;
    else if (col < DTR_ + S_)  g_bc[((size_t)row * S_ + (col - DTR_)) * 2]       = v;
    else if (col < XDN_)       g_bc[((size_t)row * S_ + (col - DTR_ - S_)) * 2 + 1] = v;
}

__global__ void __launch_bounds__(256, 2) k_gemm2(const __half* __restrict__ A,
                                                  const __half* __restrict__ Bt,
                                                  float* __restrict__ C) {
    extern __shared__ __half g2s[];
    int tid = threadIdx.x;
    int lane = tid & 31, wid = tid >> 5;
    int wm = wid >> 1, wn = wid & 1;
    int gid = lane >> 2, tig = lane & 3;
    int m0 = blockIdx.x * 128;

    uint32_t sa0 = (uint32_t)__cvta_generic_to_shared(&g2s[0]);
    uint32_t sb0 = sa0 + 2 * G2AST_;

    int a_row = ((lane >> 3) & 1) * 8 + (lane & 7);
    int a_kof = (lane >> 4) * 8;
    int b2_row = ((lane >> 4) & 1) * 8 + (lane & 7);
    int b2_kof = ((lane >> 3) & 1) * 8;

    float acc[2][4][4];
    #pragma unroll
    for (int i = 0; i < 2; i++)
        #pragma unroll
        for (int j = 0; j < 4; j++)
            #pragma unroll
            for (int q = 0; q < 4; q++) acc[i][j][q] = 0.f;

    #pragma unroll
    for (int i = 0; i < 4; i++) {
        int f = tid + i * 256;
        int row = f >> 3, c8 = f & 7;
        cp_async16(sa0 + row * (G2P_ * 2) + c8 * 16,
                   &A[(size_t)(m0 + row) * DI_ + c8 * 8]);
    }
    #pragma unroll
    for (int i = 0; i < 2; i++) {
        int f = tid + i * 256;
        int row = f >> 3, c8 = f & 7;
        cp_async16(sb0 + row * (G2P_ * 2) + c8 * 16,
                   &Bt[(size_t)row * DI_ + c8 * 8]);
    }
    CP_COMMIT();

    for (int c = 0; c < 12; c++) {
        int cur = c & 1;
        if (c < 11) {
            int nxt = (c + 1) & 1;
            #pragma unroll
            for (int i = 0; i < 4; i++) {
                int f = tid + i * 256;
                int row = f >> 3, c8 = f & 7;
                cp_async16(sa0 + nxt * G2AST_ + row * (G2P_ * 2) + c8 * 16,
                           &A[(size_t)(m0 + row) * DI_ + (c + 1) * 64 + c8 * 8]);
            }
            #pragma unroll
            for (int i = 0; i < 2; i++) {
                int f = tid + i * 256;
                int row = f >> 3, c8 = f & 7;
                cp_async16(sb0 + nxt * G2BST_ + row * (G2P_ * 2) + c8 * 16,
                           &Bt[(size_t)row * DI_ + (c + 1) * 64 + c8 * 8]);
            }
            CP_COMMIT();
            CP_WAIT(1);
        } else {
            CP_WAIT(0);
        }
        __syncthreads();
        uint32_t pa = sa0 + cur * G2AST_;
        uint32_t pb = sb0 + cur * G2BST_;
        #pragma unroll
        for (int kk = 0; kk < 64; kk += 16) {
            uint32_t af[2][4], bf[4][2];
            #pragma unroll
            for (int mt = 0; mt < 2; mt++) {
                int r = wm * 32 + mt * 16 + a_row;
                ldsm_x4(af[mt][0], af[mt][1], af[mt][2], af[mt][3],
                        pa + r * (G2P_ * 2) + (kk + a_kof) * 2);
            }
            #pragma unroll
            for (int p = 0; p < 2; p++) {
                int r = wn * 32 + p * 16 + b2_row;
                ldsm_x4(bf[2 * p][0], bf[2 * p][1], bf[2 * p + 1][0], bf[2 * p + 1][1],
                        pb + r * (G2P_ * 2) + (kk + b2_kof) * 2);
            }
            #pragma unroll
            for (int mt = 0; mt < 2; mt++)
                #pragma unroll
                for (int nt = 0; nt < 4; nt++)
                    mma_f16(acc[mt][nt], af[mt], bf[nt]);
        }
        __syncthreads();
    }
    #pragma unroll
    for (int mt = 0; mt < 2; mt++) {
        int row = m0 + wm * 32 + mt * 16 + gid;
        #pragma unroll
        for (int nt = 0; nt < 4; nt++) {
            int col = wn * 32 + nt * 8 + 2 * tig;
            g2_store(row,     col,     acc[mt][nt][0], C);
            g2_store(row,     col + 1, acc[mt][nt][1], C);
            g2_store(row + 8, col,     acc[mt][nt][2], C);
            g2_store(row + 8, col + 1, acc[mt][nt][3], C);
        }
    }
}

// ======================= conv (K=4) + SiLU — 8 tokens/thread sliding window =======================
__global__ void k_conv(const float* __restrict__ conv_w, const float* __restrict__ conv_b) {
    int idx = blockIdx.x * 256 + threadIdx.x;        // T_/8 * 384 threads
    if (idx >= (T_ / 8) * (DI_ / 2)) return;
    int dh = idx % (DI_ / 2);
    int tg = idx / (DI_ / 2);
    int di = dh * 2;
    int t0 = tg * 8;
    int l0 = t0 & (L_ - 1);
    float cw[2][KC_];
    #pragma unroll
    for (int k = 0; k < KC_; k++) {
        cw[0][k] = conv_w[di * KC_ + k];
        cw[1][k] = conv_w[(di + 1) * KC_ + k];
    }
    float2 bias = make_float2(conv_b[di], conv_b[di + 1]);
    float2 w[11];
    #pragma unroll
    for (int k = 0; k < 11; k++) {
        int ll = l0 - 3 + k;
        w[k] = (ll >= 0) ? __half22float2(*(const __half2*)&g_xzh[(size_t)(t0 - 3 + k) * NI_ + di])
                         : make_float2(0.f, 0.f);
    }
    #pragma unroll
    for (int i = 0; i < 8; i++) {
        float2 acc = bias;
        #pragma unroll
        for (int k = 0; k < KC_; k++) {
            acc.x = fmaf(cw[0][k], w[i + k].x, acc.x);
            acc.y = fmaf(cw[1][k], w[i + k].y, acc.y);
        }
        float sx = acc.x / (1.f + __expf(-acc.x));
        float sy = acc.y / (1.f + __expf(-acc.y));
        *(__half2*)&g_xch[(size_t)(t0 + i) * DI_ + di] = __floats2half2_rn(sx, sy);
    }
}

// ======================= dt = softplus(dt_r @ W_dt + bias) -> half, MUFU softplus ==========
__global__ void k_dt(const float* __restrict__ W_dt, const float* __restrict__ dt_bias) {
    __shared__ float s_dtr[16][DTR_];
    int t0 = blockIdx.x * 16;
    int tid = threadIdx.x;
    if (tid < 16 * DTR_) {
        int tt = tid / DTR_, rr = tid % DTR_;
        s_dtr[tt][rr] = g_xdbl[(size_t)(t0 + tt) * XDN_ + rr];
    }
    __syncthreads();
    int di = tid;
    float bias = dt_bias[di];
    float acc[16];
    #pragma unroll
    for (int tt = 0; tt < 16; tt++) acc[tt] = bias;
    for (int rr = 0; rr < DTR_; rr++) {
        float w = W_dt[rr * DI_ + di];
        #pragma unroll
        for (int tt = 0; tt < 16; tt++) acc[tt] = fmaf(s_dtr[tt][rr], w, acc[tt]);
    }
    #pragma unroll
    for (int tt = 0; tt < 16; tt++) {
        float v = acc[tt];
        float sp = (v > 15.f) ? v : __logf(1.f + __expf(v));
        g_dth[(size_t)(t0 + tt) * DI_ + di] = __float2half_rn(sp);
    }
}

// ======================= selective scan — verified single-pass pipeline ======
#define SCT_  32
#define SNC_  (L_ / SCT_)
#define SST_  4

__global__ void __launch_bounds__(64) k_scan2(const float* __restrict__ A_log) {
    __shared__ __half sdt[SST_][SCT_ * 16];
    __shared__ __half sxc[SST_][SCT_ * 16];
    __shared__ float2 sbc[SST_][SCT_ * 16];
    int dg = blockIdx.x, b = blockIdx.y;
    int tid = threadIdx.x;
    int di_l = tid >> 2;
    int grp  = tid & 3;
    int di = dg * 16 + di_l;
    float Ag[4], h[4] = {0.f, 0.f, 0.f, 0.f};
    #pragma unroll
    for (int j = 0; j < 4; j++)
        Ag[j] = -__expf(A_log[di * S_ + grp * 4 + j]) * 1.44269504f;
    size_t tbase = (size_t)b * L_;
    const __half* dtp = g_dth + tbase * DI_ + dg * 16;
    const __half* xcp = g_xch + tbase * DI_ + dg * 16;
    const float2* bc  = (const float2*)g_bc + tbase * S_;

    uint32_t st0 = (uint32_t)__cvta_generic_to_shared(&sdt[0][0]);
    uint32_t sx0 = (uint32_t)__cvta_generic_to_shared(&sxc[0][0]);
    uint32_t sb0 = (uint32_t)__cvta_generic_to_shared(&sbc[0][0]);

    #pragma unroll
    for (int st = 0; st < SST_ - 1; st++) {
        int t0 = st * SCT_;
        {
            int tok = tid >> 1, q = tid & 1;
            cp_async16(st0 + st * (SCT_ * 16 * 2) + tok * 32 + q * 16,
                       dtp + (size_t)(t0 + tok) * DI_ + q * 8);
            cp_async16(sx0 + st * (SCT_ * 16 * 2) + tok * 32 + q * 16,
                       xcp + (size_t)(t0 + tok) * DI_ + q * 8);
        }
        #pragma unroll
        for (int i = 0; i < 4; i++) {
            int idx = tid + i * 64;
            int tok = idx >> 3, q = idx & 7;
            cp_async16(sb0 + st * (SCT_ * 16 * 8) + tok * 128 + q * 16,
                       bc + (size_t)(t0 + tok) * S_ + q * 2);
        }
        CP_COMMIT();
    }

    for (int c = 0; c < SNC_; c++) {
        CP_WAIT(2);
        __syncthreads();
        if (c + SST_ - 1 < SNC_) {
            int st = (c + SST_ - 1) & (SST_ - 1);
            int t0 = (c + SST_ - 1) * SCT_;
            {
                int tok = tid >> 1, q = tid & 1;
                cp_async16(st0 + st * (SCT_ * 16 * 2) + tok * 32 + q * 16,
                           dtp + (size_t)(t0 + tok) * DI_ + q * 8);
                cp_async16(sx0 + st * (SCT_ * 16 * 2) + tok * 32 + q * 16,
                           xcp + (size_t)(t0 + tok) * DI_ + q * 8);
            }
            #pragma unroll
            for (int i = 0; i < 4; i++) {
                int idx = tid + i * 64;
                int tok = idx >> 3, q = idx & 7;
                cp_async16(sb0 + st * (SCT_ * 16 * 8) + tok * 128 + q * 16,
                           bc + (size_t)(t0 + tok) * S_ + q * 2);
            }
        }
        CP_COMMIT();

        const __half* pd = sdt[c & (SST_ - 1)];
        const __half* px = sxc[c & (SST_ - 1)];
        const float4* pb4 = (const float4*)sbc[c & (SST_ - 1)];
        size_t gy = (tbase + (size_t)c * SCT_) * DI_ + di;
        #pragma unroll 8
        for (int j = 0; j < SCT_; j++) {
            float dtv = __half2float(pd[j * 16 + di_l]);
            float xv  = __half2float(px[j * 16 + di_l]);
            float4 q0 = pb4[j * 8 + grp * 2];
            float4 q1 = pb4[j * 8 + grp * 2 + 1];
            float dxx = dtv * xv;
            float dA0 = exp2f(dtv * Ag[0]);
            float dA1 = exp2f(dtv * Ag[1]);
            float dA2 = exp2f(dtv * Ag[2]);
            float dA3 = exp2f(dtv * Ag[3]);
            h[0] = fmaf(dA0, h[0], dxx * q0.x);
            h[1] = fmaf(dA1, h[1], dxx * q0.z);
            h[2] = fmaf(dA2, h[2], dxx * q1.x);
            h[3] = fmaf(dA3, h[3], dxx * q1.z);
            float yp = h[0] * q0.y + h[1] * q0.w + h[2] * q1.y + h[3] * q1.w;
            yp += __shfl_xor_sync(0xffffffffu, yp, 1);
            yp += __shfl_xor_sync(0xffffffffu, yp, 2);
            if (grp == 0) g_yh[gy + (size_t)j * DI_] = __float2half_rn(yp);
        }
    }
}

// ======================= gate + Dskip + partial pool, 2 di/thread =======================
__global__ void k_ypart(const float* __restrict__ Dskip) {
    int dh    = blockIdx.x * 128 + threadIdx.x;
    int chunk = blockIdx.y;
    int b     = blockIdx.z;
    int di = dh * 2;
    float2 ds = *(const float2*)&Dskip[di];
    float2 acc = make_float2(0.f, 0.f);
    int t0 = b * L_ + chunk * 64;
    for (int i = 0; i < 64; i++) {
        int t = t0 + i;
        float2 z  = __half22float2(*(const __half2*)&g_xzh[(size_t)t * NI_ + DI_ + di]);
        float2 y  = __half22float2(*(const __half2*)&g_yh[(size_t)t * DI_ + di]);
        float2 xc = __half22float2(*(const __half2*)&g_xch[(size_t)t * DI_ + di]);
        float szx = z.x / (1.f + __expf(-z.x));
        float szy = z.y / (1.f + __expf(-z.y));
        acc.x = fmaf(y.x + xc.x * ds.x, szx, acc.x);
        acc.y = fmaf(y.y + xc.y * ds.y, szy, acc.y);
    }
    *(float2*)&g_ypart[(size_t)(chunk * B_ + b) * DI_ + di] = acc;
}
__global__ void k_ymean() {
    int i = blockIdx.x * 256 + threadIdx.x;
    float acc = 0.f;
    for (int c = 0; c < 64; c++) acc += g_ypart[(size_t)c * B_ * DI_ + i];
    g_ym[i] = acc * (1.f / L_);
}

// ======================= x-mean / pooled / head =======================
__global__ void k_xpart(const float* __restrict__ x) {
    int d = threadIdx.x;
    int chunk = blockIdx.x;
    int b = blockIdx.y;
    float acc = 0.f;
    int t0 = b * L_ + chunk * 64;
    for (int i = 0; i < 64; i++) acc += x[(size_t)(t0 + i) * D_ + d];
    g_xpart[(size_t)(chunk * B_ + b) * D_ + d] = acc;
}
__global__ void k_xmean() {
    int i = blockIdx.x * 256 + threadIdx.x;
    float acc = 0.f;
    for (int c = 0; c < 64; c++) acc += g_xpart[(size_t)c * B_ * D_ + i];
    g_xmean[i] = acc * (1.f / L_);
}
__global__ void k_pooled(const float* __restrict__ W_out) {
    int d = threadIdx.x;
    int b = blockIdx.x;
    float acc = g_xmean[b * D_ + d];
    for (int di = 0; di < DI_; di++)
        acc = fmaf(g_ym[b * DI_ + di], W_out[(size_t)di * D_ + d], acc);
    g_pooled[b * D_ + d] = acc;
}
__global__ void k_head(const float* __restrict__ W_fc, const float* __restrict__ b_fc,
                       const float* __restrict__ gamma, const float* __restrict__ beta,
                       const float* __restrict__ W_cls, const float* __restrict__ b_cls,
                       float* __restrict__ out) {
    __shared__ float sp[B_][D_];
    __shared__ float sh[B_][256];
    int tid = threadIdx.x;
    for (int i = tid; i < B_ * D_; i += 256) sp[i / D_][i % D_] = g_pooled[i];
    __syncthreads();
    int j = tid;
    float hv[B_];
    #pragma unroll
    for (int b = 0; b < B_; b++) hv[b] = b_fc[j];
    for (int k = 0; k < D_; k++) {
        float w = W_fc[(size_t)k * 256 + j];
        #pragma unroll
        for (int b = 0; b < B_; b++) hv[b] = fmaf(sp[b][k], w, hv[b]);
    }
    float mu = 0.f;
    #pragma unroll
    for (int b = 0; b < B_; b++) mu += hv[b];
    mu *= (1.f / B_);
    float var = 0.f;
    #pragma unroll
    for (int b = 0; b < B_; b++) { float dd = hv[b] - mu; var += dd * dd; }
    var *= (1.f / B_);
    float rs = rsqrtf(var + EPS_);
    float g = gamma[j], bt = beta[j];
    #pragma unroll
    for (int b = 0; b < B_; b++) {
        float v = (hv[b] - mu) * rs * g + bt;
        sh[b][j] = v > 0.f ? v : 0.f;
    }
    __syncthreads();
    for (int o = tid; o < B_ * NC_; o += 256) {
        int b = o / NC_, c = o % NC_;
        float acc = b_cls[c];
        for (int k = 0; k < 256; k++) acc = fmaf(sh[b][k], W_cls[k * NC_ + c], acc);
        out[o] = acc;
    }
}

// ======================= launch =======================
extern "C" void kernel_launch(void* const* d_in, const int* in_sizes, int n_in,
                              void* d_out, int out_size) {
    const float* x       = (const float*)d_in[0];
    const float* ln_w    = (const float*)d_in[1];
    const float* W_in    = (const float*)d_in[2];
    const float* conv_w  = (const float*)d_in[3];
    const float* conv_b  = (const float*)d_in[4];
    const float* W_xproj = (const float*)d_in[5];
    const float* W_dt    = (const float*)d_in[6];
    const float* dt_bias = (const float*)d_in[7];
    const float* A_log   = (const float*)d_in[8];
    const float* Dskip   = (const float*)d_in[9];
    const float* W_out   = (const float*)d_in[10];
    const float* W_fc    = (const float*)d_in[11];
    const float* b_fc    = (const float*)d_in[12];
    const float* bn_g    = (const float*)d_in[13];
    const float* bn_b    = (const float*)d_in[14];
    const float* W_cls   = (const float*)d_in[15];
    const float* b_cls   = (const float*)d_in[16];
    float* out = (float*)d_out;

    __half *p_xnh, *p_wth, *p_xzh, *p_xch, *p_wt2h;
    cudaGetSymbolAddress((void**)&p_xnh,  g_xnh);
    cudaGetSymbolAddress((void**)&p_wth,  g_wth);
    cudaGetSymbolAddress((void**)&p_xzh,  g_xzh);
    cudaGetSymbolAddress((void**)&p_xch,  g_xch);
    cudaGetSymbolAddress((void**)&p_wt2h, g_wt2h);
    float* p_xdbl;
    cudaGetSymbolAddress((void**)&p_xdbl, g_xdbl);

    static int s_attr_done = 0;
    if (!s_attr_done) {
        cudaFuncSetAttribute(k_gemm1, cudaFuncAttributeMaxDynamicSharedMemorySize, G1SM_);
        cudaFuncSetAttribute(k_gemm2, cudaFuncAttributeMaxDynamicSharedMemorySize, G2SM_);
        s_attr_done = 1;
    }

    // 1. RMSNorm (half out) + weight transposes
    k_rmsnorm<<<T_, 128>>>(x, ln_w);
    k_wt<<<dim3(D_ / 32, NI_ / 32), 256>>>(W_in);
    k_wt2<<<dim3(DI_ / 32, 2), 256>>>(W_xproj);
    // 2. xz = xn @ W_in — fp16 mma
    k_gemm1<<<dim3(NI_ / 128, T_ / 128), 256, G1SM_>>>(p_xnh, p_wth, p_xzh);
    // 3. conv + silu — 8 tokens/thread sliding window
    k_conv<<<((T_ / 8) * (DI_ / 2) + 255) / 256, 256>>>(conv_w, conv_b);
    // 4. x_dbl = xc @ W_xproj — fp16 mma, fused bc scatter
    k_gemm2<<<T_ / 128, 256, G2SM_>>>(p_xch, p_wt2h, p_xdbl);
    // 5. dt — MUFU softplus
    k_dt<<<T_ / 16, DI_>>>(W_dt, dt_bias);
    // 6. selective scan
    k_scan2<<<dim3(DI_ / 16, B_), 64>>>(A_log);
    // 7. gate+pool + x-mean + pooled + head
    k_ypart<<<dim3(DI_ / 2 / 128, 64, B_), 128>>>(Dskip);
    k_ymean<<<(B_ * DI_) / 256, 256>>>();
    k_xpart<<<dim3(64, B_), D_>>>(x);
    k_xmean<<<(B_ * D_) / 256, 256>>>();
    k_pooled<<<B_, D_>>>(W_out);
    k_head<<<1, 256>>>(W_fc, b_fc, bn_g, bn_b, W_cls, b_cls, out);
}